// round 12
// baseline (speedup 1.0000x reference)
#include <cuda_runtime.h>
#include <cuda_fp16.h>
#include <cstdint>

#define BATCH 4
#define HEADS 16
#define SEQ   1024
#define HD    64
#define BH    (BATCH*HEADS)
#define NPE   2047

__device__ __half g_hidH[(size_t)BATCH * SEQ * 1024];
__device__ __half g_WH[3][(size_t)1024 * 1024];
__device__ __half g_Qh [(size_t)BH * SEQ * HD];
__device__ __half g_Kh [(size_t)BH * SEQ * HD];
__device__ __half g_Vh [(size_t)BH * SEQ * HD];
__device__ __half g_PEh[(size_t)2048 * HD];

// ---------------- helpers ----------------
__device__ __forceinline__ void mma_f16(float* c,
    uint32_t a0, uint32_t a1, uint32_t a2, uint32_t a3,
    uint32_t b0, uint32_t b1)
{
    asm volatile(
        "mma.sync.aligned.m16n8k16.row.col.f32.f16.f16.f32 "
        "{%0,%1,%2,%3}, {%4,%5,%6,%7}, {%8,%9}, {%0,%1,%2,%3};"
        : "+f"(c[0]), "+f"(c[1]), "+f"(c[2]), "+f"(c[3])
        : "r"(a0), "r"(a1), "r"(a2), "r"(a3), "r"(b0), "r"(b1));
}
__device__ __forceinline__ void mma_f16c(uint32_t* c,
    uint32_t a0, uint32_t a1, uint32_t a2, uint32_t a3,
    uint32_t b0, uint32_t b1)
{
    asm volatile(
        "mma.sync.aligned.m16n8k16.row.col.f16.f16.f16.f16 "
        "{%0,%1}, {%2,%3,%4,%5}, {%6,%7}, {%0,%1};"
        : "+r"(c[0]), "+r"(c[1])
        : "r"(a0), "r"(a1), "r"(a2), "r"(a3), "r"(b0), "r"(b1));
}
__device__ __forceinline__ uint32_t s2u(const void* p) {
    return (uint32_t)__cvta_generic_to_shared(p);
}
__device__ __forceinline__ uint32_t swz(uint32_t off) {
    return off ^ ((off >> 3) & 0x70);
}
__device__ __forceinline__ void ldsm4(uint32_t& r0, uint32_t& r1,
                                      uint32_t& r2, uint32_t& r3, uint32_t a)
{
    asm volatile("ldmatrix.sync.aligned.m8n8.x4.shared.b16 {%0,%1,%2,%3}, [%4];"
        : "=r"(r0), "=r"(r1), "=r"(r2), "=r"(r3) : "r"(a));
}
__device__ __forceinline__ void ldsm4t(uint32_t& r0, uint32_t& r1,
                                       uint32_t& r2, uint32_t& r3, uint32_t a)
{
    asm volatile("ldmatrix.sync.aligned.m8n8.x4.trans.shared.b16 {%0,%1,%2,%3}, [%4];"
        : "=r"(r0), "=r"(r1), "=r"(r2), "=r"(r3) : "r"(a));
}
__device__ __forceinline__ void stsm4(uint32_t a, uint32_t r0, uint32_t r1,
                                      uint32_t r2, uint32_t r3)
{
    asm volatile("stmatrix.sync.aligned.m8n8.x4.shared.b16 [%0], {%1,%2,%3,%4};"
        :: "r"(a), "r"(r0), "r"(r1), "r"(r2), "r"(r3));
}
__device__ __forceinline__ uint32_t packh2(float x, float y) {
    __half2 h = __floats2half2_rn(x, y);
    return *(uint32_t*)&h;
}
__device__ __forceinline__ uint32_t ex2h2(__half2 t) {
    uint32_t r;
    asm("ex2.approx.f16x2 %0, %1;" : "=r"(r) : "r"(*(uint32_t*)&t));
    return r;
}
__device__ __forceinline__ void cp16(uint32_t smem, const void* gmem) {
    asm volatile("cp.async.cg.shared.global [%0], [%1], 16;" :: "r"(smem), "l"(gmem));
}

// ---------------------------------------------------------------------------
// K0: convert hid + weights to fp16; z=4 builds the fp16 PE table.
// ---------------------------------------------------------------------------
__global__ void __launch_bounds__(256) k_prep(
    const float* __restrict__ hid, const float* __restrict__ wq,
    const float* __restrict__ wk,  const float* __restrict__ wv,
    const float* __restrict__ de)
{
    const int z = blockIdx.z;
    if (z == 4) {
        if (blockIdx.x >= 128) return;
        size_t i = ((size_t)blockIdx.x * 256 + threadIdx.x) * 4;
        int row = (int)(i >> 6);
        uint2 o;
        if (row < NPE) {
            float4 v = *(const float4*)&de[i];
            o.x = packh2(v.x, v.y);
            o.y = packh2(v.z, v.w);
        } else {
            o.x = 0u; o.y = 0u;
        }
        *(uint2*)&g_PEh[i] = o;
        return;
    }
    const float* src;
    __half* dst;
    int nblk;
    if (z == 0) { src = hid; dst = g_hidH; nblk = 4096; }
    else {
        src = (z == 1) ? wq : (z == 2) ? wk : wv;
        dst = g_WH[z - 1];
        nblk = 1024;
    }
    if (blockIdx.x >= nblk) return;
    size_t i = ((size_t)blockIdx.x * 256 + threadIdx.x) * 4;
    float4 v = *(const float4*)&src[i];
    uint2 o;
    o.x = packh2(v.x, v.y);
    o.y = packh2(v.z, v.w);
    *(uint2*)&dst[i] = o;
}

// ---------------------------------------------------------------------------
// K1: QKV projection, fp16 mma, cp.async 2-stage pipeline (unchanged).
// ---------------------------------------------------------------------------
__global__ void __launch_bounds__(256) k_qkv_mma(
    const float* __restrict__ bq, const float* __restrict__ bk,
    const float* __restrict__ bv)
{
    extern __shared__ __half smh[];
    const int which = blockIdx.z;
    const __half* Ag = g_hidH;
    const __half* Bg = g_WH[which];
    const float* bi  = (which == 0) ? bq : (which == 1) ? bk : bv;
    __half* Out      = (which == 0) ? g_Qh : (which == 1) ? g_Kh : g_Vh;

    const int m0 = blockIdx.x * 128;
    const int n0 = blockIdx.y * 128;

    __half* AsB = smh;
    __half* BsB = smh + 2 * 128 * 72;

    const int t  = threadIdx.x;
    const int w  = t >> 5;
    const int ln = t & 31;
    const int mW = (w & 3) * 32;
    const int nW = (w >> 2) * 64;
    const int gr = ln >> 2;
    const int gt = ln & 3;
    const int lrA = ln & 15, lcA = (ln >> 4) << 3;
    const int lrB = (ln & 7) + ((ln >> 4) << 3), lcB = ((ln >> 3) & 1) << 3;

    float acc[2][8][4];
    #pragma unroll
    for (int i = 0; i < 2; i++)
        #pragma unroll
        for (int j = 0; j < 8; j++)
            #pragma unroll
            for (int q = 0; q < 4; q++) acc[i][j][q] = 0.f;

    auto issue = [&](int buf, int k0) {
        __half* As = AsB + buf * 128 * 72;
        __half* Bs = BsB + buf * 128 * 72;
        #pragma unroll
        for (int i = 0; i < 4; i++) {
            int idx = t + 256 * i;
            int row = idx >> 3;
            int sg  = (idx & 7) << 3;
            cp16(s2u(&As[row * 72 + sg]), &Ag[(size_t)(m0 + row) * 1024 + k0 + sg]);
            cp16(s2u(&Bs[row * 72 + sg]), &Bg[(size_t)(n0 + row) * 1024 + k0 + sg]);
        }
        asm volatile("cp.async.commit_group;");
    };

    issue(0, 0);

    for (int it = 0; it < 16; it++) {
        const int cur = it & 1;
        if (it < 15) {
            issue(cur ^ 1, 64 * (it + 1));
            asm volatile("cp.async.wait_group 1;");
        } else {
            asm volatile("cp.async.wait_group 0;");
        }
        __syncthreads();

        const uint32_t ab = s2u(AsB + cur * 128 * 72);
        const uint32_t bb = s2u(BsB + cur * 128 * 72);

        #pragma unroll
        for (int ks = 0; ks < 4; ks++) {
            const int kk = 16 * ks;
            uint32_t a[2][4];
            #pragma unroll
            for (int ms = 0; ms < 2; ms++)
                ldsm4(a[ms][0], a[ms][1], a[ms][2], a[ms][3],
                      ab + ((mW + 16 * ms + lrA) * 72 + kk + lcA) * 2);
            #pragma unroll
            for (int nb = 0; nb < 4; nb++) {
                uint32_t b0, b1, b2, b3;
                ldsm4(b0, b1, b2, b3,
                      bb + ((nW + 16 * nb + lrB) * 72 + kk + lcB) * 2);
                mma_f16(acc[0][2*nb  ], a[0][0], a[0][1], a[0][2], a[0][3], b0, b1);
                mma_f16(acc[0][2*nb+1], a[0][0], a[0][1], a[0][2], a[0][3], b2, b3);
                mma_f16(acc[1][2*nb  ], a[1][0], a[1][1], a[1][2], a[1][3], b0, b1);
                mma_f16(acc[1][2*nb+1], a[1][0], a[1][1], a[1][2], a[1][3], b2, b3);
            }
        }
        __syncthreads();
    }

    #pragma unroll
    for (int ms = 0; ms < 2; ms++) {
        #pragma unroll
        for (int s = 0; s < 8; s++) {
            int n  = n0 + nW + 8 * s + 2 * gt;
            int h  = n >> 6, dd = n & 63;
            float b0 = bi[n], b1 = bi[n + 1];
            #pragma unroll
            for (int hh = 0; hh < 2; hh++) {
                int m  = m0 + mW + 16 * ms + gr + 8 * hh;
                int bb2 = m >> 10, ss = m & 1023;
                size_t flat = (((size_t)bb2 * HEADS + h) * SEQ + ss) * HD + dd;
                *(uint32_t*)&Out[flat] =
                    packh2(acc[ms][s][2*hh] + b0, acc[ms][s][2*hh+1] + b1);
            }
        }
    }
}

// ---------------------------------------------------------------------------
// K2: fused flash attention.
//  - PE ring: two 64-row slots keyed by chunk parity; 1 chunk loaded/iter.
//  - QK n-block gK reuses ak quadrants as B-fragments (ldsm lane maps match).
// smem: Kh[2][64][64]@0, Vh[2][64][64]@16384, PE slots 2x8KB @32768,
//       QPb[64][80]@49152, KPb[64][80]@59392  -> 69632 B, 3 CTAs/SM.
// ---------------------------------------------------------------------------
#define OFF_KH   0
#define OFF_VH   16384
#define OFF_PEH  32768
#define OFF_QPB  49152
#define OFF_KPB  59392
#define FLASH_SMEM 69632

__global__ void __launch_bounds__(128, 3) k_flash(float* __restrict__ out)
{
    extern __shared__ char dynsmem[];
    const uint32_t base = s2u(dynsmem);

    const int bx = blockIdx.x;
    const int l0 = bx * 64;
    const int bh = blockIdx.y;
    const int b  = bh >> 4, h = bh & 15;

    const int t  = threadIdx.x;
    const int w  = t >> 5;
    const int ln = t & 31;
    const int gr = ln >> 2;
    const int gt = ln & 3;
    const int mBlk = w * 16;
    const int gK   = 3 - w;
    const int mKP  = gK * 16;
    const int sB   = 2 * w;

    const int lrA = ln & 15, lcA = (ln >> 4) << 3;
    const int lrB = (ln & 7) + ((ln >> 4) << 3), lcB = ((ln >> 3) & 1) << 3;

    const size_t bhbase = (size_t)bh * SEQ * HD;
    __half* QPbp = (__half*)(dynsmem + OFF_QPB);
    __half* KPbp = (__half*)(dynsmem + OFF_KPB);

    auto issue_kv = [&](int buf, int r0) {
        #pragma unroll
        for (int i = 0; i < 4; i++) {
            int idx = t + 128 * i;
            int row = idx >> 3;
            int g   = (idx & 7) << 3;
            uint32_t so = swz((row * 64 + g) * 2);
            cp16(base + OFF_KH + buf * 8192 + so,
                 &g_Kh[bhbase + (size_t)(r0 + row) * HD + g]);
            cp16(base + OFF_VH + buf * 8192 + so,
                 &g_Vh[bhbase + (size_t)(r0 + row) * HD + g]);
        }
        asm volatile("cp.async.commit_group;");
    };
    // load absolute 64-row PE chunk into slot (chunk & 1)
    auto issue_pe = [&](int chunk) {
        const int slot = chunk & 1;
        #pragma unroll
        for (int i = 0; i < 4; i++) {
            int idx = t + 128 * i;          // 0..511
            int row = idx >> 3;             // 0..63
            int g   = (idx & 7) << 3;
            cp16(base + OFF_PEH + slot * 8192 + swz((row * 64 + g) * 2),
                 &g_PEh[((size_t)chunk * 64 + row) * HD + g]);
        }
        asm volatile("cp.async.commit_group;");
    };

    issue_kv(0, 0);
    issue_pe(bx + 15);
    issue_pe(bx + 16);

    // ---- stage Q via QPb, hoist A-fragments ----
    #pragma unroll
    for (int i = 0; i < 8; i++) {
        int f = t + 128 * i;
        int row = f >> 4;
        int c4  = (f & 15) << 2;
        *(uint2*)&QPbp[row * 80 + c4] =
            *(const uint2*)&g_Qh[bhbase + (size_t)(l0 + row) * HD + c4];
    }
    __syncthreads();
    uint32_t aq[4][4];
    {
        const uint32_t qb = base + OFF_QPB;
        #pragma unroll
        for (int ks = 0; ks < 4; ks++)
            ldsm4(aq[ks][0], aq[ks][1], aq[ks][2], aq[ks][3],
                  qb + ((mBlk + lrA) * 80 + 16 * ks + lcA) * 2);
    }

    const __half2 CL2 = __float2half2_rn(0.18033688f);   // log2(e)/8
    const float  CF  = 0.18033688f;
    const uint32_t ONES = 0x3C003C00u;

    float accO[9][4];
    #pragma unroll
    for (int s = 0; s < 9; s++)
        #pragma unroll
        for (int q = 0; q < 4; q++) accO[s][q] = 0.f;

    for (int it = 0; it < 16; it++) {
        const int cur = it & 1;
        const int slotLo = (bx + 15 - it) & 1;   // slot of PE chunk m0/64

        asm volatile("cp.async.wait_group 0;");
        __syncthreads();                       // B1
        if (it < 15) issue_kv(cur ^ 1, 64 * (it + 1));

        const uint32_t peb = base + OFF_PEH;
        const uint32_t kb  = base + OFF_KH + cur * 8192;
        const uint32_t vb  = base + OFF_VH + cur * 8192;

        // ---- merged QP/KP band GEMM (shared B-frags) ----
        uint32_t ak[4][4];
        #pragma unroll
        for (int ks = 0; ks < 4; ks++)
            ldsm4(ak[ks][0], ak[ks][1], ak[ks][2], ak[ks][3],
                  kb + swz(((mKP + lrA) * 64 + 16 * ks + lcA) * 2));
        {
            uint32_t pq[10][2], pk[10][2];
            #pragma unroll
            for (int s = 0; s < 10; s++) {
                pq[s][0] = pq[s][1] = 0u;
                pk[s][0] = pk[s][1] = 0u;
            }
            #pragma unroll
            for (int ks = 0; ks < 4; ks++) {
                #pragma unroll
                for (int p5 = 0; p5 < 5; p5++) {
                    int blk2 = sB + 2 * p5;                 // n16-block pair idx
                    int slot = (slotLo + (blk2 >> 3)) & 1;  // pe ring slot
                    int rloc = (8 * blk2) & 63;             // row within slot
                    uint32_t b0, b1, b2, b3;
                    ldsm4(b0, b1, b2, b3,
                          peb + slot * 8192 +
                          swz(((rloc + lrB) * 64 + 16 * ks + lcB) * 2));
                    mma_f16c(pq[2*p5  ], aq[ks][0], aq[ks][1], aq[ks][2], aq[ks][3], b0, b1);
                    mma_f16c(pq[2*p5+1], aq[ks][0], aq[ks][1], aq[ks][2], aq[ks][3], b2, b3);
                    mma_f16c(pk[2*p5  ], ak[ks][0], ak[ks][1], ak[ks][2], ak[ks][3], b0, b1);
                    mma_f16c(pk[2*p5+1], ak[ks][0], ak[ks][1], ak[ks][2], ak[ks][3], b2, b3);
                }
            }
            #pragma unroll
            for (int p5 = 0; p5 < 5; p5++) {
                int colb = 8 * (2 * p5 + (ln >> 4));
                stsm4(base + OFF_QPB + ((mBlk + lrA) * 80 + colb) * 2,
                      pq[2*p5][0], pq[2*p5][1], pq[2*p5+1][0], pq[2*p5+1][1]);
                stsm4(base + OFF_KPB + ((mKP + lrA) * 80 + colb) * 2,
                      pk[2*p5][0], pk[2*p5][1], pk[2*p5+1][0], pk[2*p5+1][1]);
            }
        }

        // ---- QK^T: own n-block (gK) B-frags come from ak registers ----
        float cqk[8][4];
        #pragma unroll
        for (int s = 0; s < 8; s++)
            #pragma unroll
            for (int q = 0; q < 4; q++) cqk[s][q] = 0.f;
        #pragma unroll
        for (int ks = 0; ks < 4; ks++) {
            const int kk = 16 * ks;
            #pragma unroll
            for (int nb = 0; nb < 4; nb++) {
                uint32_t b0, b1, b2, b3;
                if (nb == gK) {
                    b0 = ak[ks][0]; b1 = ak[ks][2];
                    b2 = ak[ks][1]; b3 = ak[ks][3];
                } else {
                    ldsm4(b0, b1, b2, b3,
                          kb + swz(((16 * nb + lrB) * 64 + kk + lcB) * 2));
                }
                mma_f16(cqk[2*nb  ], aq[ks][0], aq[ks][1], aq[ks][2], aq[ks][3], b0, b1);
                mma_f16(cqk[2*nb+1], aq[ks][0], aq[ks][1], aq[ks][2], aq[ks][3], b2, b3);
            }
        }
        __syncthreads();                       // B2: QPb/KPb ready, PE reads done
        if (it < 15) issue_pe(bx + 14 - it);   // new chunk for next iter

        // ---- gather + exp (half2); P stays in regs as PV A-frags ----
        uint32_t hl[8], hh[8];
        {
            const int l2a = mBlk + gr;
            const int l2b = l2a + 8;
            #pragma unroll
            for (int s8 = 0; s8 < 8; s8++) {
                int rr0 = 8 * s8 + 2 * gt;
                int rr1 = rr0 + 1;
                __half2 qpA = __halves2half2(QPbp[l2a * 80 + gr - rr0 + 63],
                                             QPbp[l2a * 80 + gr - rr1 + 63]);
                __half2 kpA = __halves2half2(KPbp[rr0 * 80 + l2a - (rr0 & 15) + 15],
                                             KPbp[rr1 * 80 + l2a - (rr1 & 15) + 15]);
                __half2 hsA = __floats2half2_rn(cqk[s8][0] * CF, cqk[s8][1] * CF);
                hl[s8] = ex2h2(__hfma2(__hadd2(qpA, kpA), CL2, hsA));

                __half2 qpB = __halves2half2(QPbp[l2b * 80 + gr + 8 - rr0 + 63],
                                             QPbp[l2b * 80 + gr + 8 - rr1 + 63]);
                __half2 kpB = __halves2half2(KPbp[rr0 * 80 + l2b - (rr0 & 15) + 15],
                                             KPbp[rr1 * 80 + l2b - (rr1 & 15) + 15]);
                __half2 hsB = __floats2half2_rn(cqk[s8][2] * CF, cqk[s8][3] * CF);
                hh[s8] = ex2h2(__hfma2(__hadd2(qpB, kpB), CL2, hsB));
            }
        }

        // ---- PV + ones-fragment row sums ----
        {
            #pragma unroll
            for (int s = 0; s < 8; s++) {
                int dcol = 8 * s;
                uint32_t v0, v1, v2, v3, v4, v5, v6, v7;
                ldsm4t(v0, v1, v2, v3, vb + swz(((ln     ) * 64 + dcol) * 2));
                ldsm4t(v4, v5, v6, v7, vb + swz(((32 + ln) * 64 + dcol) * 2));
                mma_f16(accO[s], hl[0], hh[0], hl[1], hh[1], v0, v1);
                mma_f16(accO[s], hl[2], hh[2], hl[3], hh[3], v2, v3);
                mma_f16(accO[s], hl[4], hh[4], hl[5], hh[5], v4, v5);
                mma_f16(accO[s], hl[6], hh[6], hl[7], hh[7], v6, v7);
            }
            mma_f16(accO[8], hl[0], hh[0], hl[1], hh[1], ONES, ONES);
            mma_f16(accO[8], hl[2], hh[2], hl[3], hh[3], ONES, ONES);
            mma_f16(accO[8], hl[4], hh[4], hl[5], hh[5], ONES, ONES);
            mma_f16(accO[8], hl[6], hh[6], hl[7], hh[7], ONES, ONES);
        }
    }

    float inv0 = 1.0f / accO[8][0];
    float inv1 = 1.0f / accO[8][2];

    #pragma unroll
    for (int s = 0; s < 8; s++) {
        int dd = 8 * s + 2 * gt;
        int l  = l0 + mBlk + gr;
        *(float2*)&out[((size_t)b * SEQ + l) * (HEADS * HD) + h * HD + dd] =
            make_float2(accO[s][0] * inv0, accO[s][1] * inv0);
        *(float2*)&out[((size_t)b * SEQ + l + 8) * (HEADS * HD) + h * HD + dd] =
            make_float2(accO[s][2] * inv1, accO[s][3] * inv1);
    }
}

// ---------------------------------------------------------------------------
extern "C" void kernel_launch(void* const* d_in, const int* in_sizes, int n_in,
                              void* d_out, int out_size)
{
    const float* hid = (const float*)d_in[0];
    const float* wq  = (const float*)d_in[1];
    const float* bq  = (const float*)d_in[2];
    const float* wk  = (const float*)d_in[3];
    const float* bk  = (const float*)d_in[4];
    const float* wv  = (const float*)d_in[5];
    const float* bv  = (const float*)d_in[6];
    const float* de  = (const float*)d_in[7];
    float* out = (float*)d_out;

    const int qkv_smem = 4 * 128 * 72 * (int)sizeof(__half);   // 73728
    cudaFuncSetAttribute(k_qkv_mma,
                         cudaFuncAttributeMaxDynamicSharedMemorySize, qkv_smem);
    cudaFuncSetAttribute(k_flash,
                         cudaFuncAttributeMaxDynamicSharedMemorySize, FLASH_SMEM);

    k_prep<<<dim3(4096, 1, 5), 256>>>(hid, wq, wk, wv, de);
    k_qkv_mma<<<dim3(32, 8, 3), 256, qkv_smem>>>(bq, bk, bv);
    k_flash<<<dim3(16, BH), 128, FLASH_SMEM>>>(out);
}

// round 13
// speedup vs baseline: 1.0216x; 1.0216x over previous
#include <cuda_runtime.h>
#include <cuda_fp16.h>
#include <cstdint>

#define BATCH 4
#define HEADS 16
#define SEQ   1024
#define HD    64
#define BH    (BATCH*HEADS)
#define NPE   2047

__device__ __half g_hidH[(size_t)BATCH * SEQ * 1024];
__device__ __half g_WH[3][(size_t)1024 * 1024];
__device__ __half g_Qh [(size_t)BH * SEQ * HD];
__device__ __half g_Kh [(size_t)BH * SEQ * HD];
__device__ __half g_Vh [(size_t)BH * SEQ * HD];
__device__ __half g_PEh[(size_t)2048 * HD];

// ---------------- helpers ----------------
__device__ __forceinline__ void mma_f16(float* c,
    uint32_t a0, uint32_t a1, uint32_t a2, uint32_t a3,
    uint32_t b0, uint32_t b1)
{
    asm volatile(
        "mma.sync.aligned.m16n8k16.row.col.f32.f16.f16.f32 "
        "{%0,%1,%2,%3}, {%4,%5,%6,%7}, {%8,%9}, {%0,%1,%2,%3};"
        : "+f"(c[0]), "+f"(c[1]), "+f"(c[2]), "+f"(c[3])
        : "r"(a0), "r"(a1), "r"(a2), "r"(a3), "r"(b0), "r"(b1));
}
__device__ __forceinline__ void mma_f16c(uint32_t* c,
    uint32_t a0, uint32_t a1, uint32_t a2, uint32_t a3,
    uint32_t b0, uint32_t b1)
{
    asm volatile(
        "mma.sync.aligned.m16n8k16.row.col.f16.f16.f16.f16 "
        "{%0,%1}, {%2,%3,%4,%5}, {%6,%7}, {%0,%1};"
        : "+r"(c[0]), "+r"(c[1])
        : "r"(a0), "r"(a1), "r"(a2), "r"(a3), "r"(b0), "r"(b1));
}
__device__ __forceinline__ uint32_t s2u(const void* p) {
    return (uint32_t)__cvta_generic_to_shared(p);
}
__device__ __forceinline__ uint32_t swz(uint32_t off) {
    return off ^ ((off >> 3) & 0x70);
}
__device__ __forceinline__ void ldsm4(uint32_t& r0, uint32_t& r1,
                                      uint32_t& r2, uint32_t& r3, uint32_t a)
{
    asm volatile("ldmatrix.sync.aligned.m8n8.x4.shared.b16 {%0,%1,%2,%3}, [%4];"
        : "=r"(r0), "=r"(r1), "=r"(r2), "=r"(r3) : "r"(a));
}
__device__ __forceinline__ void ldsm4t(uint32_t& r0, uint32_t& r1,
                                       uint32_t& r2, uint32_t& r3, uint32_t a)
{
    asm volatile("ldmatrix.sync.aligned.m8n8.x4.trans.shared.b16 {%0,%1,%2,%3}, [%4];"
        : "=r"(r0), "=r"(r1), "=r"(r2), "=r"(r3) : "r"(a));
}
__device__ __forceinline__ void stsm4(uint32_t a, uint32_t r0, uint32_t r1,
                                      uint32_t r2, uint32_t r3)
{
    asm volatile("stmatrix.sync.aligned.m8n8.x4.shared.b16 [%0], {%1,%2,%3,%4};"
        :: "r"(a), "r"(r0), "r"(r1), "r"(r2), "r"(r3));
}
__device__ __forceinline__ uint32_t packh2(float x, float y) {
    __half2 h = __floats2half2_rn(x, y);
    return *(uint32_t*)&h;
}
__device__ __forceinline__ uint32_t ex2h2(__half2 t) {
    uint32_t r;
    asm("ex2.approx.f16x2 %0, %1;" : "=r"(r) : "r"(*(uint32_t*)&t));
    return r;
}
__device__ __forceinline__ void cp16(uint32_t smem, const void* gmem) {
    asm volatile("cp.async.cg.shared.global [%0], [%1], 16;" :: "r"(smem), "l"(gmem));
}

// ---------------------------------------------------------------------------
// K0: fp16 conversion of hid/weights/PE table. 2 float4 per thread.
// z=0: hid (2048 blk), z=1..3: weights (512 blk), z=4: PE (64 blk).
// ---------------------------------------------------------------------------
__global__ void __launch_bounds__(256) k_prep(
    const float* __restrict__ hid, const float* __restrict__ wq,
    const float* __restrict__ wk,  const float* __restrict__ wv,
    const float* __restrict__ de)
{
    const int z = blockIdx.z;
    if (z == 4) {
        if (blockIdx.x >= 64) return;
        size_t i = ((size_t)blockIdx.x * 256 + threadIdx.x) * 8;
        int row = (int)(i >> 6);
        uint4 o;
        if (row < NPE) {
            float4 v0 = *(const float4*)&de[i];
            float4 v1 = *(const float4*)&de[i + 4];
            o.x = packh2(v0.x, v0.y); o.y = packh2(v0.z, v0.w);
            o.z = packh2(v1.x, v1.y); o.w = packh2(v1.z, v1.w);
        } else {
            o.x = o.y = o.z = o.w = 0u;
        }
        *(uint4*)&g_PEh[i] = o;
        return;
    }
    const float* src;
    __half* dst;
    int nblk;
    if (z == 0) { src = hid; dst = g_hidH; nblk = 2048; }
    else {
        src = (z == 1) ? wq : (z == 2) ? wk : wv;
        dst = g_WH[z - 1];
        nblk = 512;
    }
    if (blockIdx.x >= nblk) return;
    size_t i = ((size_t)blockIdx.x * 256 + threadIdx.x) * 8;
    float4 v0 = *(const float4*)&src[i];
    float4 v1 = *(const float4*)&src[i + 4];
    uint4 o;
    o.x = packh2(v0.x, v0.y); o.y = packh2(v0.z, v0.w);
    o.z = packh2(v1.x, v1.y); o.w = packh2(v1.z, v1.w);
    *(uint4*)&dst[i] = o;
}

// ---------------------------------------------------------------------------
// K1: QKV projection, fp16 mma, cp.async 3-STAGE pipeline, ONE barrier/iter.
// Block tile 128x128x64, 8 warps, warp tile 32x64.
// smem: 3 stages x (A[128][72]+B[128][72]) fp16 = 110592 B.
// ---------------------------------------------------------------------------
#define QKV_STAGE (128 * 72)           // halves per matrix per stage
#define QKV_SMEM  (3 * 2 * QKV_STAGE * 2)

__global__ void __launch_bounds__(256) k_qkv_mma(
    const float* __restrict__ bq, const float* __restrict__ bk,
    const float* __restrict__ bv)
{
    extern __shared__ __half smh[];
    const int which = blockIdx.z;
    const __half* Ag = g_hidH;
    const __half* Bg = g_WH[which];
    const float* bi  = (which == 0) ? bq : (which == 1) ? bk : bv;
    __half* Out      = (which == 0) ? g_Qh : (which == 1) ? g_Kh : g_Vh;

    const int m0 = blockIdx.x * 128;
    const int n0 = blockIdx.y * 128;

    const int t  = threadIdx.x;
    const int w  = t >> 5;
    const int ln = t & 31;
    const int mW = (w & 3) * 32;
    const int nW = (w >> 2) * 64;
    const int gr = ln >> 2;
    const int gt = ln & 3;
    const int lrA = ln & 15, lcA = (ln >> 4) << 3;
    const int lrB = (ln & 7) + ((ln >> 4) << 3), lcB = ((ln >> 3) & 1) << 3;

    float acc[2][8][4];
    #pragma unroll
    for (int i = 0; i < 2; i++)
        #pragma unroll
        for (int j = 0; j < 8; j++)
            #pragma unroll
            for (int q = 0; q < 4; q++) acc[i][j][q] = 0.f;

    auto issue = [&](int stg, int k0) {
        __half* As = smh + stg * 2 * QKV_STAGE;
        __half* Bs = As + QKV_STAGE;
        #pragma unroll
        for (int i = 0; i < 4; i++) {
            int idx = t + 256 * i;
            int row = idx >> 3;
            int sg  = (idx & 7) << 3;
            cp16(s2u(&As[row * 72 + sg]), &Ag[(size_t)(m0 + row) * 1024 + k0 + sg]);
            cp16(s2u(&Bs[row * 72 + sg]), &Bg[(size_t)(n0 + row) * 1024 + k0 + sg]);
        }
        asm volatile("cp.async.commit_group;");
    };

    issue(0, 0);
    issue(1, 64);

    for (int it = 0; it < 16; it++) {
        const int cur = it % 3;
        if (it < 15) asm volatile("cp.async.wait_group 1;");
        else         asm volatile("cp.async.wait_group 0;");
        __syncthreads();                     // single barrier per iter
        if (it < 14) issue((it + 2) % 3, 64 * (it + 2));

        const uint32_t ab = s2u(smh + cur * 2 * QKV_STAGE);
        const uint32_t bb = ab + QKV_STAGE * 2;

        #pragma unroll
        for (int ks = 0; ks < 4; ks++) {
            const int kk = 16 * ks;
            uint32_t a[2][4];
            #pragma unroll
            for (int ms = 0; ms < 2; ms++)
                ldsm4(a[ms][0], a[ms][1], a[ms][2], a[ms][3],
                      ab + ((mW + 16 * ms + lrA) * 72 + kk + lcA) * 2);
            #pragma unroll
            for (int nb = 0; nb < 4; nb++) {
                uint32_t b0, b1, b2, b3;
                ldsm4(b0, b1, b2, b3,
                      bb + ((nW + 16 * nb + lrB) * 72 + kk + lcB) * 2);
                mma_f16(acc[0][2*nb  ], a[0][0], a[0][1], a[0][2], a[0][3], b0, b1);
                mma_f16(acc[0][2*nb+1], a[0][0], a[0][1], a[0][2], a[0][3], b2, b3);
                mma_f16(acc[1][2*nb  ], a[1][0], a[1][1], a[1][2], a[1][3], b0, b1);
                mma_f16(acc[1][2*nb+1], a[1][0], a[1][1], a[1][2], a[1][3], b2, b3);
            }
        }
    }

    #pragma unroll
    for (int ms = 0; ms < 2; ms++) {
        #pragma unroll
        for (int s = 0; s < 8; s++) {
            int n  = n0 + nW + 8 * s + 2 * gt;
            int h  = n >> 6, dd = n & 63;
            float b0 = bi[n], b1 = bi[n + 1];
            #pragma unroll
            for (int hh = 0; hh < 2; hh++) {
                int m  = m0 + mW + 16 * ms + gr + 8 * hh;
                int bb2 = m >> 10, ss = m & 1023;
                size_t flat = (((size_t)bb2 * HEADS + h) * SEQ + ss) * HD + dd;
                *(uint32_t*)&Out[flat] =
                    packh2(acc[ms][s][2*hh] + b0, acc[ms][s][2*hh+1] + b1);
            }
        }
    }
}

// ---------------------------------------------------------------------------
// K2: fused flash attention (proven R10 structure, unchanged).
// smem: Kh[2][64][64]@0, Vh[2][64][64]@16384, PEh[128][64]@32768,
//       QPb[64][80]@49152, KPb[64][80]@59392 -> 69632 B, 3 CTAs/SM.
// ---------------------------------------------------------------------------
#define OFF_KH   0
#define OFF_VH   16384
#define OFF_PEH  32768
#define OFF_QPB  49152
#define OFF_KPB  59392
#define FLASH_SMEM 69632

__global__ void __launch_bounds__(128, 3) k_flash(float* __restrict__ out)
{
    extern __shared__ char dynsmem[];
    const uint32_t base = s2u(dynsmem);

    const int l0 = blockIdx.x * 64;
    const int bh = blockIdx.y;
    const int b  = bh >> 4, h = bh & 15;

    const int t  = threadIdx.x;
    const int w  = t >> 5;
    const int ln = t & 31;
    const int gr = ln >> 2;
    const int gt = ln & 3;
    const int mBlk = w * 16;
    const int gK   = 3 - w;
    const int mKP  = gK * 16;
    const int sB   = 2 * w;

    const int lrA = ln & 15, lcA = (ln >> 4) << 3;
    const int lrB = (ln & 7) + ((ln >> 4) << 3), lcB = ((ln >> 3) & 1) << 3;

    const size_t bhbase = (size_t)bh * SEQ * HD;
    __half* QPbp = (__half*)(dynsmem + OFF_QPB);
    __half* KPbp = (__half*)(dynsmem + OFF_KPB);

    auto issue_kv = [&](int buf, int r0) {
        #pragma unroll
        for (int i = 0; i < 4; i++) {
            int idx = t + 128 * i;
            int row = idx >> 3;
            int g   = (idx & 7) << 3;
            uint32_t so = swz((row * 64 + g) * 2);
            cp16(base + OFF_KH + buf * 8192 + so,
                 &g_Kh[bhbase + (size_t)(r0 + row) * HD + g]);
            cp16(base + OFF_VH + buf * 8192 + so,
                 &g_Vh[bhbase + (size_t)(r0 + row) * HD + g]);
        }
        asm volatile("cp.async.commit_group;");
    };
    auto issue_pe = [&](int r0) {
        const int m0 = l0 - r0 + 960;
        #pragma unroll
        for (int i = 0; i < 8; i++) {
            int idx = t + 128 * i;
            int row = idx >> 3;
            int g   = (idx & 7) << 3;
            cp16(base + OFF_PEH + swz((row * 64 + g) * 2),
                 &g_PEh[(size_t)(m0 + row) * HD + g]);
        }
        asm volatile("cp.async.commit_group;");
    };

    issue_kv(0, 0);
    issue_pe(0);

    // ---- stage Q via QPb (stride 80), hoist A-fragments ----
    #pragma unroll
    for (int i = 0; i < 8; i++) {
        int f = t + 128 * i;
        int row = f >> 4;
        int c4  = (f & 15) << 2;
        *(uint2*)&QPbp[row * 80 + c4] =
            *(const uint2*)&g_Qh[bhbase + (size_t)(l0 + row) * HD + c4];
    }
    __syncthreads();
    uint32_t aq[4][4];
    {
        const uint32_t qb = base + OFF_QPB;
        #pragma unroll
        for (int ks = 0; ks < 4; ks++)
            ldsm4(aq[ks][0], aq[ks][1], aq[ks][2], aq[ks][3],
                  qb + ((mBlk + lrA) * 80 + 16 * ks + lcA) * 2);
    }

    const __half2 CL2 = __float2half2_rn(0.18033688f);   // log2(e)/8
    const float  CF  = 0.18033688f;
    const uint32_t ONES = 0x3C003C00u;

    float accO[9][4];
    #pragma unroll
    for (int s = 0; s < 9; s++)
        #pragma unroll
        for (int q = 0; q < 4; q++) accO[s][q] = 0.f;

    for (int it = 0; it < 16; it++) {
        const int cur = it & 1;

        asm volatile("cp.async.wait_group 0;");
        __syncthreads();                       // B1
        if (it < 15) issue_kv(cur ^ 1, 64 * (it + 1));

        const uint32_t peb = base + OFF_PEH;
        const uint32_t kb  = base + OFF_KH + cur * 8192;
        const uint32_t vb  = base + OFF_VH + cur * 8192;

        // ---- merged QP/KP band GEMM ----
        {
            uint32_t ak[4][4];
            #pragma unroll
            for (int ks = 0; ks < 4; ks++)
                ldsm4(ak[ks][0], ak[ks][1], ak[ks][2], ak[ks][3],
                      kb + swz(((mKP + lrA) * 64 + 16 * ks + lcA) * 2));

            uint32_t pq[10][2], pk[10][2];
            #pragma unroll
            for (int s = 0; s < 10; s++) {
                pq[s][0] = pq[s][1] = 0u;
                pk[s][0] = pk[s][1] = 0u;
            }
            #pragma unroll
            for (int ks = 0; ks < 4; ks++) {
                #pragma unroll
                for (int p5 = 0; p5 < 5; p5++) {
                    int nB = 8 * (sB + 2 * p5);
                    uint32_t b0, b1, b2, b3;
                    ldsm4(b0, b1, b2, b3,
                          peb + swz(((nB + lrB) * 64 + 16 * ks + lcB) * 2));
                    mma_f16c(pq[2*p5  ], aq[ks][0], aq[ks][1], aq[ks][2], aq[ks][3], b0, b1);
                    mma_f16c(pq[2*p5+1], aq[ks][0], aq[ks][1], aq[ks][2], aq[ks][3], b2, b3);
                    mma_f16c(pk[2*p5  ], ak[ks][0], ak[ks][1], ak[ks][2], ak[ks][3], b0, b1);
                    mma_f16c(pk[2*p5+1], ak[ks][0], ak[ks][1], ak[ks][2], ak[ks][3], b2, b3);
                }
            }
            #pragma unroll
            for (int p5 = 0; p5 < 5; p5++) {
                int colb = 8 * (2 * p5 + (ln >> 4));
                stsm4(base + OFF_QPB + ((mBlk + lrA) * 80 + colb) * 2,
                      pq[2*p5][0], pq[2*p5][1], pq[2*p5+1][0], pq[2*p5+1][1]);
                stsm4(base + OFF_KPB + ((mKP + lrA) * 80 + colb) * 2,
                      pk[2*p5][0], pk[2*p5][1], pk[2*p5+1][0], pk[2*p5+1][1]);
            }
        }

        // ---- QK^T ----
        float cqk[8][4];
        #pragma unroll
        for (int s = 0; s < 8; s++)
            #pragma unroll
            for (int q = 0; q < 4; q++) cqk[s][q] = 0.f;
        #pragma unroll
        for (int ks = 0; ks < 4; ks++) {
            const int kk = 16 * ks;
            #pragma unroll
            for (int nb = 0; nb < 4; nb++) {
                uint32_t b0, b1, b2, b3;
                ldsm4(b0, b1, b2, b3,
                      kb + swz(((16 * nb + lrB) * 64 + kk + lcB) * 2));
                mma_f16(cqk[2*nb  ], aq[ks][0], aq[ks][1], aq[ks][2], aq[ks][3], b0, b1);
                mma_f16(cqk[2*nb+1], aq[ks][0], aq[ks][1], aq[ks][2], aq[ks][3], b2, b3);
            }
        }
        __syncthreads();                       // B2
        if (it < 15) issue_pe(64 * (it + 1));

        // ---- gather + exp (half2); P stays in regs ----
        uint32_t hl[8], hh[8];
        {
            const int l2a = mBlk + gr;
            const int l2b = l2a + 8;
            #pragma unroll
            for (int s8 = 0; s8 < 8; s8++) {
                int rr0 = 8 * s8 + 2 * gt;
                int rr1 = rr0 + 1;
                __half2 qpA = __halves2half2(QPbp[l2a * 80 + gr - rr0 + 63],
                                             QPbp[l2a * 80 + gr - rr1 + 63]);
                __half2 kpA = __halves2half2(KPbp[rr0 * 80 + l2a - (rr0 & 15) + 15],
                                             KPbp[rr1 * 80 + l2a - (rr1 & 15) + 15]);
                __half2 hsA = __floats2half2_rn(cqk[s8][0] * CF, cqk[s8][1] * CF);
                hl[s8] = ex2h2(__hfma2(__hadd2(qpA, kpA), CL2, hsA));

                __half2 qpB = __halves2half2(QPbp[l2b * 80 + gr + 8 - rr0 + 63],
                                             QPbp[l2b * 80 + gr + 8 - rr1 + 63]);
                __half2 kpB = __halves2half2(KPbp[rr0 * 80 + l2b - (rr0 & 15) + 15],
                                             KPbp[rr1 * 80 + l2b - (rr1 & 15) + 15]);
                __half2 hsB = __floats2half2_rn(cqk[s8][2] * CF, cqk[s8][3] * CF);
                hh[s8] = ex2h2(__hfma2(__hadd2(qpB, kpB), CL2, hsB));
            }
        }

        // ---- PV + ones-fragment row sums ----
        {
            #pragma unroll
            for (int s = 0; s < 8; s++) {
                int dcol = 8 * s;
                uint32_t v0, v1, v2, v3, v4, v5, v6, v7;
                ldsm4t(v0, v1, v2, v3, vb + swz(((ln     ) * 64 + dcol) * 2));
                ldsm4t(v4, v5, v6, v7, vb + swz(((32 + ln) * 64 + dcol) * 2));
                mma_f16(accO[s], hl[0], hh[0], hl[1], hh[1], v0, v1);
                mma_f16(accO[s], hl[2], hh[2], hl[3], hh[3], v2, v3);
                mma_f16(accO[s], hl[4], hh[4], hl[5], hh[5], v4, v5);
                mma_f16(accO[s], hl[6], hh[6], hl[7], hh[7], v6, v7);
            }
            mma_f16(accO[8], hl[0], hh[0], hl[1], hh[1], ONES, ONES);
            mma_f16(accO[8], hl[2], hh[2], hl[3], hh[3], ONES, ONES);
            mma_f16(accO[8], hl[4], hh[4], hl[5], hh[5], ONES, ONES);
            mma_f16(accO[8], hl[6], hh[6], hl[7], hh[7], ONES, ONES);
        }
    }

    float inv0 = 1.0f / accO[8][0];
    float inv1 = 1.0f / accO[8][2];

    #pragma unroll
    for (int s = 0; s < 8; s++) {
        int dd = 8 * s + 2 * gt;
        int l  = l0 + mBlk + gr;
        *(float2*)&out[((size_t)b * SEQ + l) * (HEADS * HD) + h * HD + dd] =
            make_float2(accO[s][0] * inv0, accO[s][1] * inv0);
        *(float2*)&out[((size_t)b * SEQ + l + 8) * (HEADS * HD) + h * HD + dd] =
            make_float2(accO[s][2] * inv1, accO[s][3] * inv1);
    }
}

// ---------------------------------------------------------------------------
extern "C" void kernel_launch(void* const* d_in, const int* in_sizes, int n_in,
                              void* d_out, int out_size)
{
    const float* hid = (const float*)d_in[0];
    const float* wq  = (const float*)d_in[1];
    const float* bq  = (const float*)d_in[2];
    const float* wk  = (const float*)d_in[3];
    const float* bk  = (const float*)d_in[4];
    const float* wv  = (const float*)d_in[5];
    const float* bv  = (const float*)d_in[6];
    const float* de  = (const float*)d_in[7];
    float* out = (float*)d_out;

    cudaFuncSetAttribute(k_qkv_mma,
                         cudaFuncAttributeMaxDynamicSharedMemorySize, QKV_SMEM);
    cudaFuncSetAttribute(k_flash,
                         cudaFuncAttributeMaxDynamicSharedMemorySize, FLASH_SMEM);

    k_prep<<<dim3(2048, 1, 5), 256>>>(hid, wq, wk, wv, de);
    k_qkv_mma<<<dim3(32, 8, 3), 256, QKV_SMEM>>>(bq, bk, bv);
    k_flash<<<dim3(16, BH), 128, FLASH_SMEM>>>(out);
}

// round 14
// speedup vs baseline: 1.0466x; 1.0245x over previous
#include <cuda_runtime.h>
#include <cuda_fp16.h>
#include <cstdint>

#define BATCH 4
#define HEADS 16
#define SEQ   1024
#define HD    64
#define BH    (BATCH*HEADS)
#define NPE   2047

__device__ __half g_hidH[(size_t)BATCH * SEQ * 1024];
__device__ __half g_WH[3][(size_t)1024 * 1024];
__device__ __half g_Qh [(size_t)BH * SEQ * HD];
__device__ __half g_Kh [(size_t)BH * SEQ * HD];
__device__ __half g_Vh [(size_t)BH * SEQ * HD];
__device__ __half g_PEh[(size_t)2048 * HD];

// ---------------- helpers ----------------
__device__ __forceinline__ void mma_f16(float* c,
    uint32_t a0, uint32_t a1, uint32_t a2, uint32_t a3,
    uint32_t b0, uint32_t b1)
{
    asm volatile(
        "mma.sync.aligned.m16n8k16.row.col.f32.f16.f16.f32 "
        "{%0,%1,%2,%3}, {%4,%5,%6,%7}, {%8,%9}, {%0,%1,%2,%3};"
        : "+f"(c[0]), "+f"(c[1]), "+f"(c[2]), "+f"(c[3])
        : "r"(a0), "r"(a1), "r"(a2), "r"(a3), "r"(b0), "r"(b1));
}
__device__ __forceinline__ void mma_f16c(uint32_t* c,
    uint32_t a0, uint32_t a1, uint32_t a2, uint32_t a3,
    uint32_t b0, uint32_t b1)
{
    asm volatile(
        "mma.sync.aligned.m16n8k16.row.col.f16.f16.f16.f16 "
        "{%0,%1}, {%2,%3,%4,%5}, {%6,%7}, {%0,%1};"
        : "+r"(c[0]), "+r"(c[1])
        : "r"(a0), "r"(a1), "r"(a2), "r"(a3), "r"(b0), "r"(b1));
}
__device__ __forceinline__ uint32_t s2u(const void* p) {
    return (uint32_t)__cvta_generic_to_shared(p);
}
__device__ __forceinline__ uint32_t swz(uint32_t off) {
    return off ^ ((off >> 3) & 0x70);
}
__device__ __forceinline__ void ldsm4(uint32_t& r0, uint32_t& r1,
                                      uint32_t& r2, uint32_t& r3, uint32_t a)
{
    asm volatile("ldmatrix.sync.aligned.m8n8.x4.shared.b16 {%0,%1,%2,%3}, [%4];"
        : "=r"(r0), "=r"(r1), "=r"(r2), "=r"(r3) : "r"(a));
}
__device__ __forceinline__ void ldsm4t(uint32_t& r0, uint32_t& r1,
                                       uint32_t& r2, uint32_t& r3, uint32_t a)
{
    asm volatile("ldmatrix.sync.aligned.m8n8.x4.trans.shared.b16 {%0,%1,%2,%3}, [%4];"
        : "=r"(r0), "=r"(r1), "=r"(r2), "=r"(r3) : "r"(a));
}
__device__ __forceinline__ void stsm4(uint32_t a, uint32_t r0, uint32_t r1,
                                      uint32_t r2, uint32_t r3)
{
    asm volatile("stmatrix.sync.aligned.m8n8.x4.shared.b16 [%0], {%1,%2,%3,%4};"
        :: "r"(a), "r"(r0), "r"(r1), "r"(r2), "r"(r3));
}
__device__ __forceinline__ uint32_t packh2(float x, float y) {
    __half2 h = __floats2half2_rn(x, y);
    return *(uint32_t*)&h;
}
__device__ __forceinline__ uint32_t ex2h2(__half2 t) {
    uint32_t r;
    asm("ex2.approx.f16x2 %0, %1;" : "=r"(r) : "r"(*(uint32_t*)&t));
    return r;
}
__device__ __forceinline__ void cp16(uint32_t smem, const void* gmem) {
    asm volatile("cp.async.cg.shared.global [%0], [%1], 16;" :: "r"(smem), "l"(gmem));
}

// ---------------------------------------------------------------------------
// K0: fp16 conversion of hid/weights/PE table. 2 float4 per thread.
// ---------------------------------------------------------------------------
__global__ void __launch_bounds__(256) k_prep(
    const float* __restrict__ hid, const float* __restrict__ wq,
    const float* __restrict__ wk,  const float* __restrict__ wv,
    const float* __restrict__ de)
{
    const int z = blockIdx.z;
    if (z == 4) {
        if (blockIdx.x >= 64) return;
        size_t i = ((size_t)blockIdx.x * 256 + threadIdx.x) * 8;
        int row = (int)(i >> 6);
        uint4 o;
        if (row < NPE) {
            float4 v0 = *(const float4*)&de[i];
            float4 v1 = *(const float4*)&de[i + 4];
            o.x = packh2(v0.x, v0.y); o.y = packh2(v0.z, v0.w);
            o.z = packh2(v1.x, v1.y); o.w = packh2(v1.z, v1.w);
        } else {
            o.x = o.y = o.z = o.w = 0u;
        }
        *(uint4*)&g_PEh[i] = o;
        return;
    }
    const float* src;
    __half* dst;
    int nblk;
    if (z == 0) { src = hid; dst = g_hidH; nblk = 2048; }
    else {
        src = (z == 1) ? wq : (z == 2) ? wk : wv;
        dst = g_WH[z - 1];
        nblk = 512;
    }
    if (blockIdx.x >= nblk) return;
    size_t i = ((size_t)blockIdx.x * 256 + threadIdx.x) * 8;
    float4 v0 = *(const float4*)&src[i];
    float4 v1 = *(const float4*)&src[i + 4];
    uint4 o;
    o.x = packh2(v0.x, v0.y); o.y = packh2(v0.z, v0.w);
    o.z = packh2(v1.x, v1.y); o.w = packh2(v1.z, v1.w);
    *(uint4*)&dst[i] = o;
}

// ---------------------------------------------------------------------------
// K1: QKV projection. 128 threads, 4 warps, WARP TILE 64x64 (2x2 warp grid),
// block 128x128, k-chunk 64, 3-stage cp.async, one barrier/iter.
// ldsm per MMA halved vs 32x64 warp tile. smem 110592 B -> 2 CTAs/SM.
// ---------------------------------------------------------------------------
#define QKV_STAGE (128 * 72)           // halves per matrix per stage
#define QKV_SMEM  (3 * 2 * QKV_STAGE * 2)

__global__ void __launch_bounds__(128) k_qkv_mma(
    const float* __restrict__ bq, const float* __restrict__ bk,
    const float* __restrict__ bv)
{
    extern __shared__ __half smh[];
    const int which = blockIdx.z;
    const __half* Ag = g_hidH;
    const __half* Bg = g_WH[which];
    const float* bi  = (which == 0) ? bq : (which == 1) ? bk : bv;
    __half* Out      = (which == 0) ? g_Qh : (which == 1) ? g_Kh : g_Vh;

    const int m0 = blockIdx.x * 128;
    const int n0 = blockIdx.y * 128;

    const int t  = threadIdx.x;
    const int w  = t >> 5;
    const int ln = t & 31;
    const int mW = (w & 1) * 64;
    const int nW = (w >> 1) * 64;
    const int gr = ln >> 2;
    const int gt = ln & 3;
    const int lrA = ln & 15, lcA = (ln >> 4) << 3;
    const int lrB = (ln & 7) + ((ln >> 4) << 3), lcB = ((ln >> 3) & 1) << 3;

    float acc[4][8][4];
    #pragma unroll
    for (int i = 0; i < 4; i++)
        #pragma unroll
        for (int j = 0; j < 8; j++)
            #pragma unroll
            for (int q = 0; q < 4; q++) acc[i][j][q] = 0.f;

    auto issue = [&](int stg, int k0) {
        __half* As = smh + stg * 2 * QKV_STAGE;
        __half* Bs = As + QKV_STAGE;
        #pragma unroll
        for (int i = 0; i < 8; i++) {
            int idx = t + 128 * i;          // 0..1023
            int row = idx >> 3;             // 0..127
            int sg  = (idx & 7) << 3;
            cp16(s2u(&As[row * 72 + sg]), &Ag[(size_t)(m0 + row) * 1024 + k0 + sg]);
            cp16(s2u(&Bs[row * 72 + sg]), &Bg[(size_t)(n0 + row) * 1024 + k0 + sg]);
        }
        asm volatile("cp.async.commit_group;");
    };

    issue(0, 0);
    issue(1, 64);

    for (int it = 0; it < 16; it++) {
        const int cur = it % 3;
        if (it < 15) asm volatile("cp.async.wait_group 1;");
        else         asm volatile("cp.async.wait_group 0;");
        __syncthreads();
        if (it < 14) issue((it + 2) % 3, 64 * (it + 2));

        const uint32_t ab = s2u(smh + cur * 2 * QKV_STAGE);
        const uint32_t bb = ab + QKV_STAGE * 2;

        #pragma unroll
        for (int ks = 0; ks < 4; ks++) {
            const int kk = 16 * ks;
            uint32_t a[4][4];
            #pragma unroll
            for (int ms = 0; ms < 4; ms++)
                ldsm4(a[ms][0], a[ms][1], a[ms][2], a[ms][3],
                      ab + ((mW + 16 * ms + lrA) * 72 + kk + lcA) * 2);
            #pragma unroll
            for (int nb = 0; nb < 4; nb++) {
                uint32_t b0, b1, b2, b3;
                ldsm4(b0, b1, b2, b3,
                      bb + ((nW + 16 * nb + lrB) * 72 + kk + lcB) * 2);
                #pragma unroll
                for (int ms = 0; ms < 4; ms++) {
                    mma_f16(acc[ms][2*nb  ], a[ms][0], a[ms][1], a[ms][2], a[ms][3], b0, b1);
                    mma_f16(acc[ms][2*nb+1], a[ms][0], a[ms][1], a[ms][2], a[ms][3], b2, b3);
                }
            }
        }
    }

    #pragma unroll
    for (int ms = 0; ms < 4; ms++) {
        #pragma unroll
        for (int s = 0; s < 8; s++) {
            int n  = n0 + nW + 8 * s + 2 * gt;
            int h  = n >> 6, dd = n & 63;
            float b0 = bi[n], b1 = bi[n + 1];
            #pragma unroll
            for (int hh = 0; hh < 2; hh++) {
                int m  = m0 + mW + 16 * ms + gr + 8 * hh;
                int bb2 = m >> 10, ss = m & 1023;
                size_t flat = (((size_t)bb2 * HEADS + h) * SEQ + ss) * HD + dd;
                *(uint32_t*)&Out[flat] =
                    packh2(acc[ms][s][2*hh] + b0, acc[ms][s][2*hh+1] + b1);
            }
        }
    }
}

// ---------------------------------------------------------------------------
// K2: fused flash attention (proven R10/R13 structure, unchanged).
// ---------------------------------------------------------------------------
#define OFF_KH   0
#define OFF_VH   16384
#define OFF_PEH  32768
#define OFF_QPB  49152
#define OFF_KPB  59392
#define FLASH_SMEM 69632

__global__ void __launch_bounds__(128, 3) k_flash(float* __restrict__ out)
{
    extern __shared__ char dynsmem[];
    const uint32_t base = s2u(dynsmem);

    const int l0 = blockIdx.x * 64;
    const int bh = blockIdx.y;
    const int b  = bh >> 4, h = bh & 15;

    const int t  = threadIdx.x;
    const int w  = t >> 5;
    const int ln = t & 31;
    const int gr = ln >> 2;
    const int gt = ln & 3;
    const int mBlk = w * 16;
    const int gK   = 3 - w;
    const int mKP  = gK * 16;
    const int sB   = 2 * w;

    const int lrA = ln & 15, lcA = (ln >> 4) << 3;
    const int lrB = (ln & 7) + ((ln >> 4) << 3), lcB = ((ln >> 3) & 1) << 3;

    const size_t bhbase = (size_t)bh * SEQ * HD;
    __half* QPbp = (__half*)(dynsmem + OFF_QPB);
    __half* KPbp = (__half*)(dynsmem + OFF_KPB);

    auto issue_kv = [&](int buf, int r0) {
        #pragma unroll
        for (int i = 0; i < 4; i++) {
            int idx = t + 128 * i;
            int row = idx >> 3;
            int g   = (idx & 7) << 3;
            uint32_t so = swz((row * 64 + g) * 2);
            cp16(base + OFF_KH + buf * 8192 + so,
                 &g_Kh[bhbase + (size_t)(r0 + row) * HD + g]);
            cp16(base + OFF_VH + buf * 8192 + so,
                 &g_Vh[bhbase + (size_t)(r0 + row) * HD + g]);
        }
        asm volatile("cp.async.commit_group;");
    };
    auto issue_pe = [&](int r0) {
        const int m0 = l0 - r0 + 960;
        #pragma unroll
        for (int i = 0; i < 8; i++) {
            int idx = t + 128 * i;
            int row = idx >> 3;
            int g   = (idx & 7) << 3;
            cp16(base + OFF_PEH + swz((row * 64 + g) * 2),
                 &g_PEh[(size_t)(m0 + row) * HD + g]);
        }
        asm volatile("cp.async.commit_group;");
    };

    issue_kv(0, 0);
    issue_pe(0);

    #pragma unroll
    for (int i = 0; i < 8; i++) {
        int f = t + 128 * i;
        int row = f >> 4;
        int c4  = (f & 15) << 2;
        *(uint2*)&QPbp[row * 80 + c4] =
            *(const uint2*)&g_Qh[bhbase + (size_t)(l0 + row) * HD + c4];
    }
    __syncthreads();
    uint32_t aq[4][4];
    {
        const uint32_t qb = base + OFF_QPB;
        #pragma unroll
        for (int ks = 0; ks < 4; ks++)
            ldsm4(aq[ks][0], aq[ks][1], aq[ks][2], aq[ks][3],
                  qb + ((mBlk + lrA) * 80 + 16 * ks + lcA) * 2);
    }

    const __half2 CL2 = __float2half2_rn(0.18033688f);   // log2(e)/8
    const float  CF  = 0.18033688f;
    const uint32_t ONES = 0x3C003C00u;

    float accO[9][4];
    #pragma unroll
    for (int s = 0; s < 9; s++)
        #pragma unroll
        for (int q = 0; q < 4; q++) accO[s][q] = 0.f;

    for (int it = 0; it < 16; it++) {
        const int cur = it & 1;

        asm volatile("cp.async.wait_group 0;");
        __syncthreads();                       // B1
        if (it < 15) issue_kv(cur ^ 1, 64 * (it + 1));

        const uint32_t peb = base + OFF_PEH;
        const uint32_t kb  = base + OFF_KH + cur * 8192;
        const uint32_t vb  = base + OFF_VH + cur * 8192;

        // ---- merged QP/KP band GEMM ----
        {
            uint32_t ak[4][4];
            #pragma unroll
            for (int ks = 0; ks < 4; ks++)
                ldsm4(ak[ks][0], ak[ks][1], ak[ks][2], ak[ks][3],
                      kb + swz(((mKP + lrA) * 64 + 16 * ks + lcA) * 2));

            uint32_t pq[10][2], pk[10][2];
            #pragma unroll
            for (int s = 0; s < 10; s++) {
                pq[s][0] = pq[s][1] = 0u;
                pk[s][0] = pk[s][1] = 0u;
            }
            #pragma unroll
            for (int ks = 0; ks < 4; ks++) {
                #pragma unroll
                for (int p5 = 0; p5 < 5; p5++) {
                    int nB = 8 * (sB + 2 * p5);
                    uint32_t b0, b1, b2, b3;
                    ldsm4(b0, b1, b2, b3,
                          peb + swz(((nB + lrB) * 64 + 16 * ks + lcB) * 2));
                    mma_f16c(pq[2*p5  ], aq[ks][0], aq[ks][1], aq[ks][2], aq[ks][3], b0, b1);
                    mma_f16c(pq[2*p5+1], aq[ks][0], aq[ks][1], aq[ks][2], aq[ks][3], b2, b3);
                    mma_f16c(pk[2*p5  ], ak[ks][0], ak[ks][1], ak[ks][2], ak[ks][3], b0, b1);
                    mma_f16c(pk[2*p5+1], ak[ks][0], ak[ks][1], ak[ks][2], ak[ks][3], b2, b3);
                }
            }
            #pragma unroll
            for (int p5 = 0; p5 < 5; p5++) {
                int colb = 8 * (2 * p5 + (ln >> 4));
                stsm4(base + OFF_QPB + ((mBlk + lrA) * 80 + colb) * 2,
                      pq[2*p5][0], pq[2*p5][1], pq[2*p5+1][0], pq[2*p5+1][1]);
                stsm4(base + OFF_KPB + ((mKP + lrA) * 80 + colb) * 2,
                      pk[2*p5][0], pk[2*p5][1], pk[2*p5+1][0], pk[2*p5+1][1]);
            }
        }

        // ---- QK^T ----
        float cqk[8][4];
        #pragma unroll
        for (int s = 0; s < 8; s++)
            #pragma unroll
            for (int q = 0; q < 4; q++) cqk[s][q] = 0.f;
        #pragma unroll
        for (int ks = 0; ks < 4; ks++) {
            const int kk = 16 * ks;
            #pragma unroll
            for (int nb = 0; nb < 4; nb++) {
                uint32_t b0, b1, b2, b3;
                ldsm4(b0, b1, b2, b3,
                      kb + swz(((16 * nb + lrB) * 64 + kk + lcB) * 2));
                mma_f16(cqk[2*nb  ], aq[ks][0], aq[ks][1], aq[ks][2], aq[ks][3], b0, b1);
                mma_f16(cqk[2*nb+1], aq[ks][0], aq[ks][1], aq[ks][2], aq[ks][3], b2, b3);
            }
        }
        __syncthreads();                       // B2
        if (it < 15) issue_pe(64 * (it + 1));

        // ---- gather + exp (half2); P stays in regs ----
        uint32_t hl[8], hh[8];
        {
            const int l2a = mBlk + gr;
            const int l2b = l2a + 8;
            #pragma unroll
            for (int s8 = 0; s8 < 8; s8++) {
                int rr0 = 8 * s8 + 2 * gt;
                int rr1 = rr0 + 1;
                __half2 qpA = __halves2half2(QPbp[l2a * 80 + gr - rr0 + 63],
                                             QPbp[l2a * 80 + gr - rr1 + 63]);
                __half2 kpA = __halves2half2(KPbp[rr0 * 80 + l2a - (rr0 & 15) + 15],
                                             KPbp[rr1 * 80 + l2a - (rr1 & 15) + 15]);
                __half2 hsA = __floats2half2_rn(cqk[s8][0] * CF, cqk[s8][1] * CF);
                hl[s8] = ex2h2(__hfma2(__hadd2(qpA, kpA), CL2, hsA));

                __half2 qpB = __halves2half2(QPbp[l2b * 80 + gr + 8 - rr0 + 63],
                                             QPbp[l2b * 80 + gr + 8 - rr1 + 63]);
                __half2 kpB = __halves2half2(KPbp[rr0 * 80 + l2b - (rr0 & 15) + 15],
                                             KPbp[rr1 * 80 + l2b - (rr1 & 15) + 15]);
                __half2 hsB = __floats2half2_rn(cqk[s8][2] * CF, cqk[s8][3] * CF);
                hh[s8] = ex2h2(__hfma2(__hadd2(qpB, kpB), CL2, hsB));
            }
        }

        // ---- PV + ones-fragment row sums ----
        {
            #pragma unroll
            for (int s = 0; s < 8; s++) {
                int dcol = 8 * s;
                uint32_t v0, v1, v2, v3, v4, v5, v6, v7;
                ldsm4t(v0, v1, v2, v3, vb + swz(((ln     ) * 64 + dcol) * 2));
                ldsm4t(v4, v5, v6, v7, vb + swz(((32 + ln) * 64 + dcol) * 2));
                mma_f16(accO[s], hl[0], hh[0], hl[1], hh[1], v0, v1);
                mma_f16(accO[s], hl[2], hh[2], hl[3], hh[3], v2, v3);
                mma_f16(accO[s], hl[4], hh[4], hl[5], hh[5], v4, v5);
                mma_f16(accO[s], hl[6], hh[6], hl[7], hh[7], v6, v7);
            }
            mma_f16(accO[8], hl[0], hh[0], hl[1], hh[1], ONES, ONES);
            mma_f16(accO[8], hl[2], hh[2], hl[3], hh[3], ONES, ONES);
            mma_f16(accO[8], hl[4], hh[4], hl[5], hh[5], ONES, ONES);
            mma_f16(accO[8], hl[6], hh[6], hl[7], hh[7], ONES, ONES);
        }
    }

    float inv0 = 1.0f / accO[8][0];
    float inv1 = 1.0f / accO[8][2];

    #pragma unroll
    for (int s = 0; s < 8; s++) {
        int dd = 8 * s + 2 * gt;
        int l  = l0 + mBlk + gr;
        *(float2*)&out[((size_t)b * SEQ + l) * (HEADS * HD) + h * HD + dd] =
            make_float2(accO[s][0] * inv0, accO[s][1] * inv0);
        *(float2*)&out[((size_t)b * SEQ + l + 8) * (HEADS * HD) + h * HD + dd] =
            make_float2(accO[s][2] * inv1, accO[s][3] * inv1);
    }
}

// ---------------------------------------------------------------------------
extern "C" void kernel_launch(void* const* d_in, const int* in_sizes, int n_in,
                              void* d_out, int out_size)
{
    const float* hid = (const float*)d_in[0];
    const float* wq  = (const float*)d_in[1];
    const float* bq  = (const float*)d_in[2];
    const float* wk  = (const float*)d_in[3];
    const float* bk  = (const float*)d_in[4];
    const float* wv  = (const float*)d_in[5];
    const float* bv  = (const float*)d_in[6];
    const float* de  = (const float*)d_in[7];
    float* out = (float*)d_out;

    cudaFuncSetAttribute(k_qkv_mma,
                         cudaFuncAttributeMaxDynamicSharedMemorySize, QKV_SMEM);
    cudaFuncSetAttribute(k_flash,
                         cudaFuncAttributeMaxDynamicSharedMemorySize, FLASH_SMEM);

    k_prep<<<dim3(2048, 1, 5), 256>>>(hid, wq, wk, wv, de);
    k_qkv_mma<<<dim3(32, 8, 3), 128, QKV_SMEM>>>(bq, bk, bv);
    k_flash<<<dim3(16, BH), 128, FLASH_SMEM>>>(out);
}

// round 15
// speedup vs baseline: 1.0746x; 1.0267x over previous
#include <cuda_runtime.h>
#include <cuda_fp16.h>
#include <cstdint>

#define BATCH 4
#define HEADS 16
#define SEQ   1024
#define HD    64
#define BH    (BATCH*HEADS)
#define NPE   2047

__device__ __half g_hidH[(size_t)BATCH * SEQ * 1024];
__device__ __half g_WH[3][(size_t)1024 * 1024];
__device__ __half g_Qh [(size_t)BH * SEQ * HD];
__device__ __half g_Kh [(size_t)BH * SEQ * HD];
__device__ __half g_Vh [(size_t)BH * SEQ * HD];
__device__ __half g_PEh[(size_t)2048 * HD];

// ---------------- helpers ----------------
__device__ __forceinline__ void mma_f16(float* c,
    uint32_t a0, uint32_t a1, uint32_t a2, uint32_t a3,
    uint32_t b0, uint32_t b1)
{
    asm volatile(
        "mma.sync.aligned.m16n8k16.row.col.f32.f16.f16.f32 "
        "{%0,%1,%2,%3}, {%4,%5,%6,%7}, {%8,%9}, {%0,%1,%2,%3};"
        : "+f"(c[0]), "+f"(c[1]), "+f"(c[2]), "+f"(c[3])
        : "r"(a0), "r"(a1), "r"(a2), "r"(a3), "r"(b0), "r"(b1));
}
__device__ __forceinline__ void mma_f16c(uint32_t* c,
    uint32_t a0, uint32_t a1, uint32_t a2, uint32_t a3,
    uint32_t b0, uint32_t b1)
{
    asm volatile(
        "mma.sync.aligned.m16n8k16.row.col.f16.f16.f16.f16 "
        "{%0,%1}, {%2,%3,%4,%5}, {%6,%7}, {%0,%1};"
        : "+r"(c[0]), "+r"(c[1])
        : "r"(a0), "r"(a1), "r"(a2), "r"(a3), "r"(b0), "r"(b1));
}
__device__ __forceinline__ uint32_t s2u(const void* p) {
    return (uint32_t)__cvta_generic_to_shared(p);
}
__device__ __forceinline__ uint32_t swz(uint32_t off) {
    return off ^ ((off >> 3) & 0x70);
}
__device__ __forceinline__ void ldsm4(uint32_t& r0, uint32_t& r1,
                                      uint32_t& r2, uint32_t& r3, uint32_t a)
{
    asm volatile("ldmatrix.sync.aligned.m8n8.x4.shared.b16 {%0,%1,%2,%3}, [%4];"
        : "=r"(r0), "=r"(r1), "=r"(r2), "=r"(r3) : "r"(a));
}
__device__ __forceinline__ void ldsm4t(uint32_t& r0, uint32_t& r1,
                                       uint32_t& r2, uint32_t& r3, uint32_t a)
{
    asm volatile("ldmatrix.sync.aligned.m8n8.x4.trans.shared.b16 {%0,%1,%2,%3}, [%4];"
        : "=r"(r0), "=r"(r1), "=r"(r2), "=r"(r3) : "r"(a));
}
__device__ __forceinline__ void stsm4(uint32_t a, uint32_t r0, uint32_t r1,
                                      uint32_t r2, uint32_t r3)
{
    asm volatile("stmatrix.sync.aligned.m8n8.x4.shared.b16 [%0], {%1,%2,%3,%4};"
        :: "r"(a), "r"(r0), "r"(r1), "r"(r2), "r"(r3));
}
__device__ __forceinline__ uint32_t packh2(float x, float y) {
    __half2 h = __floats2half2_rn(x, y);
    return *(uint32_t*)&h;
}
__device__ __forceinline__ uint32_t ex2h2(__half2 t) {
    uint32_t r;
    asm("ex2.approx.f16x2 %0, %1;" : "=r"(r) : "r"(*(uint32_t*)&t));
    return r;
}
__device__ __forceinline__ void cp16(uint32_t smem, const void* gmem) {
    asm volatile("cp.async.cg.shared.global [%0], [%1], 16;" :: "r"(smem), "l"(gmem));
}

// ---------------------------------------------------------------------------
// K0: fp16 conversion (unchanged from R14)
// ---------------------------------------------------------------------------
__global__ void __launch_bounds__(256) k_prep(
    const float* __restrict__ hid, const float* __restrict__ wq,
    const float* __restrict__ wk,  const float* __restrict__ wv,
    const float* __restrict__ de)
{
    const int z = blockIdx.z;
    if (z == 4) {
        if (blockIdx.x >= 64) return;
        size_t i = ((size_t)blockIdx.x * 256 + threadIdx.x) * 8;
        int row = (int)(i >> 6);
        uint4 o;
        if (row < NPE) {
            float4 v0 = *(const float4*)&de[i];
            float4 v1 = *(const float4*)&de[i + 4];
            o.x = packh2(v0.x, v0.y); o.y = packh2(v0.z, v0.w);
            o.z = packh2(v1.x, v1.y); o.w = packh2(v1.z, v1.w);
        } else {
            o.x = o.y = o.z = o.w = 0u;
        }
        *(uint4*)&g_PEh[i] = o;
        return;
    }
    const float* src;
    __half* dst;
    int nblk;
    if (z == 0) { src = hid; dst = g_hidH; nblk = 2048; }
    else {
        src = (z == 1) ? wq : (z == 2) ? wk : wv;
        dst = g_WH[z - 1];
        nblk = 512;
    }
    if (blockIdx.x >= nblk) return;
    size_t i = ((size_t)blockIdx.x * 256 + threadIdx.x) * 8;
    float4 v0 = *(const float4*)&src[i];
    float4 v1 = *(const float4*)&src[i + 4];
    uint4 o;
    o.x = packh2(v0.x, v0.y); o.y = packh2(v0.z, v0.w);
    o.z = packh2(v1.x, v1.y); o.w = packh2(v1.z, v1.w);
    *(uint4*)&dst[i] = o;
}

// ---------------------------------------------------------------------------
// K1: QKV projection. Block tile 256x128 (L2 traffic -27%), 256 threads,
// 8 warps (4 m x 2 n), warp tile 64x64, k-chunk 64, 3-stage cp.async,
// single barrier/iter. Swizzled unpadded 128B rows. smem 144KB, 1 CTA/SM.
// ---------------------------------------------------------------------------
#define QKV_AST  (256 * 64)            // halves per A stage
#define QKV_BST  (128 * 64)            // halves per B stage
#define QKV_STG  (QKV_AST + QKV_BST)   // halves per stage
#define QKV_SMEM (3 * QKV_STG * 2)     // 147456 B

__global__ void __launch_bounds__(256, 1) k_qkv_mma(
    const float* __restrict__ bq, const float* __restrict__ bk,
    const float* __restrict__ bv)
{
    extern __shared__ __half smh[];
    const int which = blockIdx.z;
    const __half* Ag = g_hidH;
    const __half* Bg = g_WH[which];
    const float* bi  = (which == 0) ? bq : (which == 1) ? bk : bv;
    __half* Out      = (which == 0) ? g_Qh : (which == 1) ? g_Kh : g_Vh;

    const int m0 = blockIdx.x * 256;
    const int n0 = blockIdx.y * 128;

    const int t  = threadIdx.x;
    const int w  = t >> 5;
    const int ln = t & 31;
    const int mW = (w & 3) * 64;
    const int nW = (w >> 2) * 64;
    const int gr = ln >> 2;
    const int gt = ln & 3;
    const int lrA = ln & 15, lcA = (ln >> 4) << 3;
    const int lrB = (ln & 7) + ((ln >> 4) << 3), lcB = ((ln >> 3) & 1) << 3;

    float acc[4][8][4];
    #pragma unroll
    for (int i = 0; i < 4; i++)
        #pragma unroll
        for (int j = 0; j < 8; j++)
            #pragma unroll
            for (int q = 0; q < 4; q++) acc[i][j][q] = 0.f;

    auto issue = [&](int stg, int k0) {
        const uint32_t as = s2u(smh) + stg * QKV_STG * 2;
        const uint32_t bs = as + QKV_AST * 2;
        #pragma unroll
        for (int i = 0; i < 8; i++) {           // A: 256x64 halves
            int idx = t + 256 * i;              // 0..2047
            int row = idx >> 3;                 // 0..255
            int g   = (idx & 7) << 3;
            cp16(as + swz((row * 64 + g) * 2),
                 &Ag[(size_t)(m0 + row) * 1024 + k0 + g]);
        }
        #pragma unroll
        for (int i = 0; i < 4; i++) {           // B: 128x64 halves
            int idx = t + 256 * i;              // 0..1023
            int row = idx >> 3;                 // 0..127
            int g   = (idx & 7) << 3;
            cp16(bs + swz((row * 64 + g) * 2),
                 &Bg[(size_t)(n0 + row) * 1024 + k0 + g]);
        }
        asm volatile("cp.async.commit_group;");
    };

    issue(0, 0);
    issue(1, 64);

    for (int it = 0; it < 16; it++) {
        const int cur = it % 3;
        if (it < 15) asm volatile("cp.async.wait_group 1;");
        else         asm volatile("cp.async.wait_group 0;");
        __syncthreads();                        // orders prev reads before issue
        if (it < 14) issue((it + 2) % 3, 64 * (it + 2));

        const uint32_t ab = s2u(smh) + cur * QKV_STG * 2;
        const uint32_t bb = ab + QKV_AST * 2;

        #pragma unroll
        for (int ks = 0; ks < 4; ks++) {
            const int kk = 16 * ks;
            uint32_t a[4][4];
            #pragma unroll
            for (int ms = 0; ms < 4; ms++)
                ldsm4(a[ms][0], a[ms][1], a[ms][2], a[ms][3],
                      ab + swz(((mW + 16 * ms + lrA) * 64 + kk + lcA) * 2));
            #pragma unroll
            for (int nb = 0; nb < 4; nb++) {
                uint32_t b0, b1, b2, b3;
                ldsm4(b0, b1, b2, b3,
                      bb + swz(((nW + 16 * nb + lrB) * 64 + kk + lcB) * 2));
                #pragma unroll
                for (int ms = 0; ms < 4; ms++) {
                    mma_f16(acc[ms][2*nb  ], a[ms][0], a[ms][1], a[ms][2], a[ms][3], b0, b1);
                    mma_f16(acc[ms][2*nb+1], a[ms][0], a[ms][1], a[ms][2], a[ms][3], b2, b3);
                }
            }
        }
    }

    #pragma unroll
    for (int ms = 0; ms < 4; ms++) {
        #pragma unroll
        for (int s = 0; s < 8; s++) {
            int n  = n0 + nW + 8 * s + 2 * gt;
            int h  = n >> 6, dd = n & 63;
            float b0 = bi[n], b1 = bi[n + 1];
            #pragma unroll
            for (int hh = 0; hh < 2; hh++) {
                int m  = m0 + mW + 16 * ms + gr + 8 * hh;
                int bb2 = m >> 10, ss = m & 1023;
                size_t flat = (((size_t)bb2 * HEADS + h) * SEQ + ss) * HD + dd;
                *(uint32_t*)&Out[flat] =
                    packh2(acc[ms][s][2*hh] + b0, acc[ms][s][2*hh+1] + b1);
            }
        }
    }
}

// ---------------------------------------------------------------------------
// K2: fused flash attention (frozen R14 structure).
// ---------------------------------------------------------------------------
#define OFF_KH   0
#define OFF_VH   16384
#define OFF_PEH  32768
#define OFF_QPB  49152
#define OFF_KPB  59392
#define FLASH_SMEM 69632

__global__ void __launch_bounds__(128, 3) k_flash(float* __restrict__ out)
{
    extern __shared__ char dynsmem[];
    const uint32_t base = s2u(dynsmem);

    const int l0 = blockIdx.x * 64;
    const int bh = blockIdx.y;
    const int b  = bh >> 4, h = bh & 15;

    const int t  = threadIdx.x;
    const int w  = t >> 5;
    const int ln = t & 31;
    const int gr = ln >> 2;
    const int gt = ln & 3;
    const int mBlk = w * 16;
    const int gK   = 3 - w;
    const int mKP  = gK * 16;
    const int sB   = 2 * w;

    const int lrA = ln & 15, lcA = (ln >> 4) << 3;
    const int lrB = (ln & 7) + ((ln >> 4) << 3), lcB = ((ln >> 3) & 1) << 3;

    const size_t bhbase = (size_t)bh * SEQ * HD;
    __half* QPbp = (__half*)(dynsmem + OFF_QPB);
    __half* KPbp = (__half*)(dynsmem + OFF_KPB);

    auto issue_kv = [&](int buf, int r0) {
        #pragma unroll
        for (int i = 0; i < 4; i++) {
            int idx = t + 128 * i;
            int row = idx >> 3;
            int g   = (idx & 7) << 3;
            uint32_t so = swz((row * 64 + g) * 2);
            cp16(base + OFF_KH + buf * 8192 + so,
                 &g_Kh[bhbase + (size_t)(r0 + row) * HD + g]);
            cp16(base + OFF_VH + buf * 8192 + so,
                 &g_Vh[bhbase + (size_t)(r0 + row) * HD + g]);
        }
        asm volatile("cp.async.commit_group;");
    };
    auto issue_pe = [&](int r0) {
        const int m0 = l0 - r0 + 960;
        #pragma unroll
        for (int i = 0; i < 8; i++) {
            int idx = t + 128 * i;
            int row = idx >> 3;
            int g   = (idx & 7) << 3;
            cp16(base + OFF_PEH + swz((row * 64 + g) * 2),
                 &g_PEh[(size_t)(m0 + row) * HD + g]);
        }
        asm volatile("cp.async.commit_group;");
    };

    issue_kv(0, 0);
    issue_pe(0);

    #pragma unroll
    for (int i = 0; i < 8; i++) {
        int f = t + 128 * i;
        int row = f >> 4;
        int c4  = (f & 15) << 2;
        *(uint2*)&QPbp[row * 80 + c4] =
            *(const uint2*)&g_Qh[bhbase + (size_t)(l0 + row) * HD + c4];
    }
    __syncthreads();
    uint32_t aq[4][4];
    {
        const uint32_t qb = base + OFF_QPB;
        #pragma unroll
        for (int ks = 0; ks < 4; ks++)
            ldsm4(aq[ks][0], aq[ks][1], aq[ks][2], aq[ks][3],
                  qb + ((mBlk + lrA) * 80 + 16 * ks + lcA) * 2);
    }

    const __half2 CL2 = __float2half2_rn(0.18033688f);
    const float  CF  = 0.18033688f;
    const uint32_t ONES = 0x3C003C00u;

    float accO[9][4];
    #pragma unroll
    for (int s = 0; s < 9; s++)
        #pragma unroll
        for (int q = 0; q < 4; q++) accO[s][q] = 0.f;

    for (int it = 0; it < 16; it++) {
        const int cur = it & 1;

        asm volatile("cp.async.wait_group 0;");
        __syncthreads();
        if (it < 15) issue_kv(cur ^ 1, 64 * (it + 1));

        const uint32_t peb = base + OFF_PEH;
        const uint32_t kb  = base + OFF_KH + cur * 8192;
        const uint32_t vb  = base + OFF_VH + cur * 8192;

        {
            uint32_t ak[4][4];
            #pragma unroll
            for (int ks = 0; ks < 4; ks++)
                ldsm4(ak[ks][0], ak[ks][1], ak[ks][2], ak[ks][3],
                      kb + swz(((mKP + lrA) * 64 + 16 * ks + lcA) * 2));

            uint32_t pq[10][2], pk[10][2];
            #pragma unroll
            for (int s = 0; s < 10; s++) {
                pq[s][0] = pq[s][1] = 0u;
                pk[s][0] = pk[s][1] = 0u;
            }
            #pragma unroll
            for (int ks = 0; ks < 4; ks++) {
                #pragma unroll
                for (int p5 = 0; p5 < 5; p5++) {
                    int nB = 8 * (sB + 2 * p5);
                    uint32_t b0, b1, b2, b3;
                    ldsm4(b0, b1, b2, b3,
                          peb + swz(((nB + lrB) * 64 + 16 * ks + lcB) * 2));
                    mma_f16c(pq[2*p5  ], aq[ks][0], aq[ks][1], aq[ks][2], aq[ks][3], b0, b1);
                    mma_f16c(pq[2*p5+1], aq[ks][0], aq[ks][1], aq[ks][2], aq[ks][3], b2, b3);
                    mma_f16c(pk[2*p5  ], ak[ks][0], ak[ks][1], ak[ks][2], ak[ks][3], b0, b1);
                    mma_f16c(pk[2*p5+1], ak[ks][0], ak[ks][1], ak[ks][2], ak[ks][3], b2, b3);
                }
            }
            #pragma unroll
            for (int p5 = 0; p5 < 5; p5++) {
                int colb = 8 * (2 * p5 + (ln >> 4));
                stsm4(base + OFF_QPB + ((mBlk + lrA) * 80 + colb) * 2,
                      pq[2*p5][0], pq[2*p5][1], pq[2*p5+1][0], pq[2*p5+1][1]);
                stsm4(base + OFF_KPB + ((mKP + lrA) * 80 + colb) * 2,
                      pk[2*p5][0], pk[2*p5][1], pk[2*p5+1][0], pk[2*p5+1][1]);
            }
        }

        float cqk[8][4];
        #pragma unroll
        for (int s = 0; s < 8; s++)
            #pragma unroll
            for (int q = 0; q < 4; q++) cqk[s][q] = 0.f;
        #pragma unroll
        for (int ks = 0; ks < 4; ks++) {
            const int kk = 16 * ks;
            #pragma unroll
            for (int nb = 0; nb < 4; nb++) {
                uint32_t b0, b1, b2, b3;
                ldsm4(b0, b1, b2, b3,
                      kb + swz(((16 * nb + lrB) * 64 + kk + lcB) * 2));
                mma_f16(cqk[2*nb  ], aq[ks][0], aq[ks][1], aq[ks][2], aq[ks][3], b0, b1);
                mma_f16(cqk[2*nb+1], aq[ks][0], aq[ks][1], aq[ks][2], aq[ks][3], b2, b3);
            }
        }
        __syncthreads();
        if (it < 15) issue_pe(64 * (it + 1));

        uint32_t hl[8], hh[8];
        {
            const int l2a = mBlk + gr;
            const int l2b = l2a + 8;
            #pragma unroll
            for (int s8 = 0; s8 < 8; s8++) {
                int rr0 = 8 * s8 + 2 * gt;
                int rr1 = rr0 + 1;
                __half2 qpA = __halves2half2(QPbp[l2a * 80 + gr - rr0 + 63],
                                             QPbp[l2a * 80 + gr - rr1 + 63]);
                __half2 kpA = __halves2half2(KPbp[rr0 * 80 + l2a - (rr0 & 15) + 15],
                                             KPbp[rr1 * 80 + l2a - (rr1 & 15) + 15]);
                __half2 hsA = __floats2half2_rn(cqk[s8][0] * CF, cqk[s8][1] * CF);
                hl[s8] = ex2h2(__hfma2(__hadd2(qpA, kpA), CL2, hsA));

                __half2 qpB = __halves2half2(QPbp[l2b * 80 + gr + 8 - rr0 + 63],
                                             QPbp[l2b * 80 + gr + 8 - rr1 + 63]);
                __half2 kpB = __halves2half2(KPbp[rr0 * 80 + l2b - (rr0 & 15) + 15],
                                             KPbp[rr1 * 80 + l2b - (rr1 & 15) + 15]);
                __half2 hsB = __floats2half2_rn(cqk[s8][2] * CF, cqk[s8][3] * CF);
                hh[s8] = ex2h2(__hfma2(__hadd2(qpB, kpB), CL2, hsB));
            }
        }

        {
            #pragma unroll
            for (int s = 0; s < 8; s++) {
                int dcol = 8 * s;
                uint32_t v0, v1, v2, v3, v4, v5, v6, v7;
                ldsm4t(v0, v1, v2, v3, vb + swz(((ln     ) * 64 + dcol) * 2));
                ldsm4t(v4, v5, v6, v7, vb + swz(((32 + ln) * 64 + dcol) * 2));
                mma_f16(accO[s], hl[0], hh[0], hl[1], hh[1], v0, v1);
                mma_f16(accO[s], hl[2], hh[2], hl[3], hh[3], v2, v3);
                mma_f16(accO[s], hl[4], hh[4], hl[5], hh[5], v4, v5);
                mma_f16(accO[s], hl[6], hh[6], hl[7], hh[7], v6, v7);
            }
            mma_f16(accO[8], hl[0], hh[0], hl[1], hh[1], ONES, ONES);
            mma_f16(accO[8], hl[2], hh[2], hl[3], hh[3], ONES, ONES);
            mma_f16(accO[8], hl[4], hh[4], hl[5], hh[5], ONES, ONES);
            mma_f16(accO[8], hl[6], hh[6], hl[7], hh[7], ONES, ONES);
        }
    }

    float inv0 = 1.0f / accO[8][0];
    float inv1 = 1.0f / accO[8][2];

    #pragma unroll
    for (int s = 0; s < 8; s++) {
        int dd = 8 * s + 2 * gt;
        int l  = l0 + mBlk + gr;
        *(float2*)&out[((size_t)b * SEQ + l) * (HEADS * HD) + h * HD + dd] =
            make_float2(accO[s][0] * inv0, accO[s][1] * inv0);
        *(float2*)&out[((size_t)b * SEQ + l + 8) * (HEADS * HD) + h * HD + dd] =
            make_float2(accO[s][2] * inv1, accO[s][3] * inv1);
    }
}

// ---------------------------------------------------------------------------
extern "C" void kernel_launch(void* const* d_in, const int* in_sizes, int n_in,
                              void* d_out, int out_size)
{
    const float* hid = (const float*)d_in[0];
    const float* wq  = (const float*)d_in[1];
    const float* bq  = (const float*)d_in[2];
    const float* wk  = (const float*)d_in[3];
    const float* bk  = (const float*)d_in[4];
    const float* wv  = (const float*)d_in[5];
    const float* bv  = (const float*)d_in[6];
    const float* de  = (const float*)d_in[7];
    float* out = (float*)d_out;

    cudaFuncSetAttribute(k_qkv_mma,
                         cudaFuncAttributeMaxDynamicSharedMemorySize, QKV_SMEM);
    cudaFuncSetAttribute(k_flash,
                         cudaFuncAttributeMaxDynamicSharedMemorySize, FLASH_SMEM);

    k_prep<<<dim3(2048, 1, 5), 256>>>(hid, wq, wk, wv, de);
    k_qkv_mma<<<dim3(16, 8, 3), 256, QKV_SMEM>>>(bq, bk, bv);
    k_flash<<<dim3(16, BH), 128, FLASH_SMEM>>>(out);
}

// round 17
// speedup vs baseline: 1.0832x; 1.0080x over previous
#include <cuda_runtime.h>
#include <cuda_fp16.h>
#include <cstdint>

#define BATCH 4
#define HEADS 16
#define SEQ   1024
#define HD    64
#define BH    (BATCH*HEADS)
#define NPE   2047

__device__ __half g_hidH[(size_t)BATCH * SEQ * 1024];
__device__ __half g_WH[3][(size_t)1024 * 1024];
__device__ __half g_Qh [(size_t)BH * SEQ * HD];
__device__ __half g_Kh [(size_t)BH * SEQ * HD];
__device__ __half g_Vh [(size_t)BH * SEQ * HD];
__device__ __half g_PEh[(size_t)2048 * HD];

// ---------------- helpers ----------------
__device__ __forceinline__ void mma_f16(float* c,
    uint32_t a0, uint32_t a1, uint32_t a2, uint32_t a3,
    uint32_t b0, uint32_t b1)
{
    asm volatile(
        "mma.sync.aligned.m16n8k16.row.col.f32.f16.f16.f32 "
        "{%0,%1,%2,%3}, {%4,%5,%6,%7}, {%8,%9}, {%0,%1,%2,%3};"
        : "+f"(c[0]), "+f"(c[1]), "+f"(c[2]), "+f"(c[3])
        : "r"(a0), "r"(a1), "r"(a2), "r"(a3), "r"(b0), "r"(b1));
}
__device__ __forceinline__ void mma_f16c(uint32_t* c,
    uint32_t a0, uint32_t a1, uint32_t a2, uint32_t a3,
    uint32_t b0, uint32_t b1)
{
    asm volatile(
        "mma.sync.aligned.m16n8k16.row.col.f16.f16.f16.f16 "
        "{%0,%1}, {%2,%3,%4,%5}, {%6,%7}, {%0,%1};"
        : "+r"(c[0]), "+r"(c[1])
        : "r"(a0), "r"(a1), "r"(a2), "r"(a3), "r"(b0), "r"(b1));
}
__device__ __forceinline__ uint32_t s2u(const void* p) {
    return (uint32_t)__cvta_generic_to_shared(p);
}
__device__ __forceinline__ uint32_t swz(uint32_t off) {
    return off ^ ((off >> 3) & 0x70);
}
__device__ __forceinline__ void ldsm4(uint32_t& r0, uint32_t& r1,
                                      uint32_t& r2, uint32_t& r3, uint32_t a)
{
    asm volatile("ldmatrix.sync.aligned.m8n8.x4.shared.b16 {%0,%1,%2,%3}, [%4];"
        : "=r"(r0), "=r"(r1), "=r"(r2), "=r"(r3) : "r"(a));
}
__device__ __forceinline__ void ldsm4t(uint32_t& r0, uint32_t& r1,
                                       uint32_t& r2, uint32_t& r3, uint32_t a)
{
    asm volatile("ldmatrix.sync.aligned.m8n8.x4.trans.shared.b16 {%0,%1,%2,%3}, [%4];"
        : "=r"(r0), "=r"(r1), "=r"(r2), "=r"(r3) : "r"(a));
}
__device__ __forceinline__ void stsm4(uint32_t a, uint32_t r0, uint32_t r1,
                                      uint32_t r2, uint32_t r3)
{
    asm volatile("stmatrix.sync.aligned.m8n8.x4.shared.b16 [%0], {%1,%2,%3,%4};"
        :: "r"(a), "r"(r0), "r"(r1), "r"(r2), "r"(r3));
}
__device__ __forceinline__ uint32_t packh2(float x, float y) {
    __half2 h = __floats2half2_rn(x, y);
    return *(uint32_t*)&h;
}
__device__ __forceinline__ uint32_t ex2h2(__half2 t) {
    uint32_t r;
    asm("ex2.approx.f16x2 %0, %1;" : "=r"(r) : "r"(*(uint32_t*)&t));
    return r;
}
__device__ __forceinline__ void cp16(uint32_t smem, const void* gmem) {
    asm volatile("cp.async.cg.shared.global [%0], [%1], 16;" :: "r"(smem), "l"(gmem));
}

// ---------------------------------------------------------------------------
// K0: fp16 conversion of hid/weights/PE table (frozen).
// ---------------------------------------------------------------------------
__global__ void __launch_bounds__(256) k_prep(
    const float* __restrict__ hid, const float* __restrict__ wq,
    const float* __restrict__ wk,  const float* __restrict__ wv,
    const float* __restrict__ de)
{
    const int z = blockIdx.z;
    if (z == 4) {
        if (blockIdx.x >= 64) return;
        size_t i = ((size_t)blockIdx.x * 256 + threadIdx.x) * 8;
        int row = (int)(i >> 6);
        uint4 o;
        if (row < NPE) {
            float4 v0 = *(const float4*)&de[i];
            float4 v1 = *(const float4*)&de[i + 4];
            o.x = packh2(v0.x, v0.y); o.y = packh2(v0.z, v0.w);
            o.z = packh2(v1.x, v1.y); o.w = packh2(v1.z, v1.w);
        } else {
            o.x = o.y = o.z = o.w = 0u;
        }
        *(uint4*)&g_PEh[i] = o;
        return;
    }
    const float* src;
    __half* dst;
    int nblk;
    if (z == 0) { src = hid; dst = g_hidH; nblk = 2048; }
    else {
        src = (z == 1) ? wq : (z == 2) ? wk : wv;
        dst = g_WH[z - 1];
        nblk = 512;
    }
    if (blockIdx.x >= nblk) return;
    size_t i = ((size_t)blockIdx.x * 256 + threadIdx.x) * 8;
    float4 v0 = *(const float4*)&src[i];
    float4 v1 = *(const float4*)&src[i + 4];
    uint4 o;
    o.x = packh2(v0.x, v0.y); o.y = packh2(v0.z, v0.w);
    o.z = packh2(v1.x, v1.y); o.w = packh2(v1.z, v1.w);
    *(uint4*)&dst[i] = o;
}

// ---------------------------------------------------------------------------
// K1: QKV projection. Block tile 256x128, 256 threads, 8 warps (4m x 2n),
// warp tile 64x64, k-chunk 64, 4-STAGE cp.async, single barrier/iter.
// Swizzled unpadded 128B rows. smem 192KB, 1 CTA/SM.
// ---------------------------------------------------------------------------
#define QKV_AST  (256 * 64)            // halves per A stage
#define QKV_BST  (128 * 64)            // halves per B stage
#define QKV_STG  (QKV_AST + QKV_BST)   // halves per stage
#define QKV_SMEM (4 * QKV_STG * 2)     // 196608 B

__global__ void __launch_bounds__(256, 1) k_qkv_mma(
    const float* __restrict__ bq, const float* __restrict__ bk,
    const float* __restrict__ bv)
{
    extern __shared__ __half smh[];
    const int which = blockIdx.z;
    const __half* Ag = g_hidH;
    const __half* Bg = g_WH[which];
    const float* bi  = (which == 0) ? bq : (which == 1) ? bk : bv;
    __half* Out      = (which == 0) ? g_Qh : (which == 1) ? g_Kh : g_Vh;

    const int m0 = blockIdx.x * 256;
    const int n0 = blockIdx.y * 128;

    const int t  = threadIdx.x;
    const int w  = t >> 5;
    const int ln = t & 31;
    const int mW = (w & 3) * 64;
    const int nW = (w >> 2) * 64;
    const int gr = ln >> 2;
    const int gt = ln & 3;
    const int lrA = ln & 15, lcA = (ln >> 4) << 3;
    const int lrB = (ln & 7) + ((ln >> 4) << 3), lcB = ((ln >> 3) & 1) << 3;

    float acc[4][8][4];
    #pragma unroll
    for (int i = 0; i < 4; i++)
        #pragma unroll
        for (int j = 0; j < 8; j++)
            #pragma unroll
            for (int q = 0; q < 4; q++) acc[i][j][q] = 0.f;

    auto issue = [&](int stg, int k0) {
        const uint32_t as = s2u(smh) + stg * QKV_STG * 2;
        const uint32_t bs = as + QKV_AST * 2;
        #pragma unroll
        for (int i = 0; i < 8; i++) {           // A: 256x64 halves
            int idx = t + 256 * i;              // 0..2047
            int row = idx >> 3;
            int g   = (idx & 7) << 3;
            cp16(as + swz((row * 64 + g) * 2),
                 &Ag[(size_t)(m0 + row) * 1024 + k0 + g]);
        }
        #pragma unroll
        for (int i = 0; i < 4; i++) {           // B: 128x64 halves
            int idx = t + 256 * i;              // 0..1023
            int row = idx >> 3;
            int g   = (idx & 7) << 3;
            cp16(bs + swz((row * 64 + g) * 2),
                 &Bg[(size_t)(n0 + row) * 1024 + k0 + g]);
        }
        asm volatile("cp.async.commit_group;");
    };

    issue(0, 0);
    issue(1, 64);
    issue(2, 128);

    for (int it = 0; it < 16; it++) {
        const int cur = it & 3;
        if (it <= 13)      asm volatile("cp.async.wait_group 2;");
        else if (it == 14) asm volatile("cp.async.wait_group 1;");
        else               asm volatile("cp.async.wait_group 0;");
        __syncthreads();                        // orders prev reads before issue
        if (it < 13) issue((it + 3) & 3, 64 * (it + 3));

        const uint32_t ab = s2u(smh) + cur * QKV_STG * 2;
        const uint32_t bb = ab + QKV_AST * 2;

        #pragma unroll
        for (int ks = 0; ks < 4; ks++) {
            const int kk = 16 * ks;
            uint32_t a[4][4];
            #pragma unroll
            for (int ms = 0; ms < 4; ms++)
                ldsm4(a[ms][0], a[ms][1], a[ms][2], a[ms][3],
                      ab + swz(((mW + 16 * ms + lrA) * 64 + kk + lcA) * 2));
            #pragma unroll
            for (int nb = 0; nb < 4; nb++) {
                uint32_t b0, b1, b2, b3;
                ldsm4(b0, b1, b2, b3,
                      bb + swz(((nW + 16 * nb + lrB) * 64 + kk + lcB) * 2));
                #pragma unroll
                for (int ms = 0; ms < 4; ms++) {
                    mma_f16(acc[ms][2*nb  ], a[ms][0], a[ms][1], a[ms][2], a[ms][3], b0, b1);
                    mma_f16(acc[ms][2*nb+1], a[ms][0], a[ms][1], a[ms][2], a[ms][3], b2, b3);
                }
            }
        }
    }

    #pragma unroll
    for (int ms = 0; ms < 4; ms++) {
        #pragma unroll
        for (int s = 0; s < 8; s++) {
            int n  = n0 + nW + 8 * s + 2 * gt;
            int h  = n >> 6, dd = n & 63;
            float b0 = bi[n], b1 = bi[n + 1];
            #pragma unroll
            for (int hh = 0; hh < 2; hh++) {
                int m  = m0 + mW + 16 * ms + gr + 8 * hh;
                int bb2 = m >> 10, ss = m & 1023;
                size_t flat = (((size_t)bb2 * HEADS + h) * SEQ + ss) * HD + dd;
                *(uint32_t*)&Out[flat] =
                    packh2(acc[ms][s][2*hh] + b0, acc[ms][s][2*hh+1] + b1);
            }
        }
    }
}

// ---------------------------------------------------------------------------
// K2: fused flash attention (frozen R14/R15 structure).
// ---------------------------------------------------------------------------
#define OFF_KH   0
#define OFF_VH   16384
#define OFF_PEH  32768
#define OFF_QPB  49152
#define OFF_KPB  59392
#define FLASH_SMEM 69632

__global__ void __launch_bounds__(128, 3) k_flash(float* __restrict__ out)
{
    extern __shared__ char dynsmem[];
    const uint32_t base = s2u(dynsmem);

    const int l0 = blockIdx.x * 64;
    const int bh = blockIdx.y;
    const int b  = bh >> 4, h = bh & 15;

    const int t  = threadIdx.x;
    const int w  = t >> 5;
    const int ln = t & 31;
    const int gr = ln >> 2;
    const int gt = ln & 3;
    const int mBlk = w * 16;
    const int gK   = 3 - w;
    const int mKP  = gK * 16;
    const int sB   = 2 * w;

    const int lrA = ln & 15, lcA = (ln >> 4) << 3;
    const int lrB = (ln & 7) + ((ln >> 4) << 3), lcB = ((ln >> 3) & 1) << 3;

    const size_t bhbase = (size_t)bh * SEQ * HD;
    __half* QPbp = (__half*)(dynsmem + OFF_QPB);
    __half* KPbp = (__half*)(dynsmem + OFF_KPB);

    auto issue_kv = [&](int buf, int r0) {
        #pragma unroll
        for (int i = 0; i < 4; i++) {
            int idx = t + 128 * i;
            int row = idx >> 3;
            int g   = (idx & 7) << 3;
            uint32_t so = swz((row * 64 + g) * 2);
            cp16(base + OFF_KH + buf * 8192 + so,
                 &g_Kh[bhbase + (size_t)(r0 + row) * HD + g]);
            cp16(base + OFF_VH + buf * 8192 + so,
                 &g_Vh[bhbase + (size_t)(r0 + row) * HD + g]);
        }
        asm volatile("cp.async.commit_group;");
    };
    auto issue_pe = [&](int r0) {
        const int m0 = l0 - r0 + 960;
        #pragma unroll
        for (int i = 0; i < 8; i++) {
            int idx = t + 128 * i;
            int row = idx >> 3;
            int g   = (idx & 7) << 3;
            cp16(base + OFF_PEH + swz((row * 64 + g) * 2),
                 &g_PEh[(size_t)(m0 + row) * HD + g]);
        }
        asm volatile("cp.async.commit_group;");
    };

    issue_kv(0, 0);
    issue_pe(0);

    #pragma unroll
    for (int i = 0; i < 8; i++) {
        int f = t + 128 * i;
        int row = f >> 4;
        int c4  = (f & 15) << 2;
        *(uint2*)&QPbp[row * 80 + c4] =
            *(const uint2*)&g_Qh[bhbase + (size_t)(l0 + row) * HD + c4];
    }
    __syncthreads();
    uint32_t aq[4][4];
    {
        const uint32_t qb = base + OFF_QPB;
        #pragma unroll
        for (int ks = 0; ks < 4; ks++)
            ldsm4(aq[ks][0], aq[ks][1], aq[ks][2], aq[ks][3],
                  qb + ((mBlk + lrA) * 80 + 16 * ks + lcA) * 2);
    }

    const __half2 CL2 = __float2half2_rn(0.18033688f);
    const float  CF  = 0.18033688f;
    const uint32_t ONES = 0x3C003C00u;

    float accO[9][4];
    #pragma unroll
    for (int s = 0; s < 9; s++)
        #pragma unroll
        for (int q = 0; q < 4; q++) accO[s][q] = 0.f;

    for (int it = 0; it < 16; it++) {
        const int cur = it & 1;

        asm volatile("cp.async.wait_group 0;");
        __syncthreads();
        if (it < 15) issue_kv(cur ^ 1, 64 * (it + 1));

        const uint32_t peb = base + OFF_PEH;
        const uint32_t kb  = base + OFF_KH + cur * 8192;
        const uint32_t vb  = base + OFF_VH + cur * 8192;

        {
            uint32_t ak[4][4];
            #pragma unroll
            for (int ks = 0; ks < 4; ks++)
                ldsm4(ak[ks][0], ak[ks][1], ak[ks][2], ak[ks][3],
                      kb + swz(((mKP + lrA) * 64 + 16 * ks + lcA) * 2));

            uint32_t pq[10][2], pk[10][2];
            #pragma unroll
            for (int s = 0; s < 10; s++) {
                pq[s][0] = pq[s][1] = 0u;
                pk[s][0] = pk[s][1] = 0u;
            }
            #pragma unroll
            for (int ks = 0; ks < 4; ks++) {
                #pragma unroll
                for (int p5 = 0; p5 < 5; p5++) {
                    int nB = 8 * (sB + 2 * p5);
                    uint32_t b0, b1, b2, b3;
                    ldsm4(b0, b1, b2, b3,
                          peb + swz(((nB + lrB) * 64 + 16 * ks + lcB) * 2));
                    mma_f16c(pq[2*p5  ], aq[ks][0], aq[ks][1], aq[ks][2], aq[ks][3], b0, b1);
                    mma_f16c(pq[2*p5+1], aq[ks][0], aq[ks][1], aq[ks][2], aq[ks][3], b2, b3);
                    mma_f16c(pk[2*p5  ], ak[ks][0], ak[ks][1], ak[ks][2], ak[ks][3], b0, b1);
                    mma_f16c(pk[2*p5+1], ak[ks][0], ak[ks][1], ak[ks][2], ak[ks][3], b2, b3);
                }
            }
            #pragma unroll
            for (int p5 = 0; p5 < 5; p5++) {
                int colb = 8 * (2 * p5 + (ln >> 4));
                stsm4(base + OFF_QPB + ((mBlk + lrA) * 80 + colb) * 2,
                      pq[2*p5][0], pq[2*p5][1], pq[2*p5+1][0], pq[2*p5+1][1]);
                stsm4(base + OFF_KPB + ((mKP + lrA) * 80 + colb) * 2,
                      pk[2*p5][0], pk[2*p5][1], pk[2*p5+1][0], pk[2*p5+1][1]);
            }
        }

        float cqk[8][4];
        #pragma unroll
        for (int s = 0; s < 8; s++)
            #pragma unroll
            for (int q = 0; q < 4; q++) cqk[s][q] = 0.f;
        #pragma unroll
        for (int ks = 0; ks < 4; ks++) {
            const int kk = 16 * ks;
            #pragma unroll
            for (int nb = 0; nb < 4; nb++) {
                uint32_t b0, b1, b2, b3;
                ldsm4(b0, b1, b2, b3,
                      kb + swz(((16 * nb + lrB) * 64 + kk + lcB) * 2));
                mma_f16(cqk[2*nb  ], aq[ks][0], aq[ks][1], aq[ks][2], aq[ks][3], b0, b1);
                mma_f16(cqk[2*nb+1], aq[ks][0], aq[ks][1], aq[ks][2], aq[ks][3], b2, b3);
            }
        }
        __syncthreads();
        if (it < 15) issue_pe(64 * (it + 1));

        uint32_t hl[8], hh[8];
        {
            const int l2a = mBlk + gr;
            const int l2b = l2a + 8;
            #pragma unroll
            for (int s8 = 0; s8 < 8; s8++) {
                int rr0 = 8 * s8 + 2 * gt;
                int rr1 = rr0 + 1;
                __half2 qpA = __halves2half2(QPbp[l2a * 80 + gr - rr0 + 63],
                                             QPbp[l2a * 80 + gr - rr1 + 63]);
                __half2 kpA = __halves2half2(KPbp[rr0 * 80 + l2a - (rr0 & 15) + 15],
                                             KPbp[rr1 * 80 + l2a - (rr1 & 15) + 15]);
                __half2 hsA = __floats2half2_rn(cqk[s8][0] * CF, cqk[s8][1] * CF);
                hl[s8] = ex2h2(__hfma2(__hadd2(qpA, kpA), CL2, hsA));

                __half2 qpB = __halves2half2(QPbp[l2b * 80 + gr + 8 - rr0 + 63],
                                             QPbp[l2b * 80 + gr + 8 - rr1 + 63]);
                __half2 kpB = __halves2half2(KPbp[rr0 * 80 + l2b - (rr0 & 15) + 15],
                                             KPbp[rr1 * 80 + l2b - (rr1 & 15) + 15]);
                __half2 hsB = __floats2half2_rn(cqk[s8][2] * CF, cqk[s8][3] * CF);
                hh[s8] = ex2h2(__hfma2(__hadd2(qpB, kpB), CL2, hsB));
            }
        }

        {
            #pragma unroll
            for (int s = 0; s < 8; s++) {
                int dcol = 8 * s;
                uint32_t v0, v1, v2, v3, v4, v5, v6, v7;
                ldsm4t(v0, v1, v2, v3, vb + swz(((ln     ) * 64 + dcol) * 2));
                ldsm4t(v4, v5, v6, v7, vb + swz(((32 + ln) * 64 + dcol) * 2));
                mma_f16(accO[s], hl[0], hh[0], hl[1], hh[1], v0, v1);
                mma_f16(accO[s], hl[2], hh[2], hl[3], hh[3], v2, v3);
                mma_f16(accO[s], hl[4], hh[4], hl[5], hh[5], v4, v5);
                mma_f16(accO[s], hl[6], hh[6], hl[7], hh[7], v6, v7);
            }
            mma_f16(accO[8], hl[0], hh[0], hl[1], hh[1], ONES, ONES);
            mma_f16(accO[8], hl[2], hh[2], hl[3], hh[3], ONES, ONES);
            mma_f16(accO[8], hl[4], hh[4], hl[5], hh[5], ONES, ONES);
            mma_f16(accO[8], hl[6], hh[6], hl[7], hh[7], ONES, ONES);
        }
    }

    float inv0 = 1.0f / accO[8][0];
    float inv1 = 1.0f / accO[8][2];

    #pragma unroll
    for (int s = 0; s < 8; s++) {
        int dd = 8 * s + 2 * gt;
        int l  = l0 + mBlk + gr;
        *(float2*)&out[((size_t)b * SEQ + l) * (HEADS * HD) + h * HD + dd] =
            make_float2(accO[s][0] * inv0, accO[s][1] * inv0);
        *(float2*)&out[((size_t)b * SEQ + l + 8) * (HEADS * HD) + h * HD + dd] =
            make_float2(accO[s][2] * inv1, accO[s][3] * inv1);
    }
}

// ---------------------------------------------------------------------------
extern "C" void kernel_launch(void* const* d_in, const int* in_sizes, int n_in,
                              void* d_out, int out_size)
{
    const float* hid = (const float*)d_in[0];
    const float* wq  = (const float*)d_in[1];
    const float* bq  = (const float*)d_in[2];
    const float* wk  = (const float*)d_in[3];
    const float* bk  = (const float*)d_in[4];
    const float* wv  = (const float*)d_in[5];
    const float* bv  = (const float*)d_in[6];
    const float* de  = (const float*)d_in[7];
    float* out = (float*)d_out;

    cudaFuncSetAttribute(k_qkv_mma,
                         cudaFuncAttributeMaxDynamicSharedMemorySize, QKV_SMEM);
    cudaFuncSetAttribute(k_flash,
                         cudaFuncAttributeMaxDynamicSharedMemorySize, FLASH_SMEM);

    k_prep<<<dim3(2048, 1, 5), 256>>>(hid, wq, wk, wv, de);
    k_qkv_mma<<<dim3(16, 8, 3), 256, QKV_SMEM>>>(bq, bk, bv);
    k_flash<<<dim3(16, BH), 128, FLASH_SMEM>>>(out);
}